// round 8
// baseline (speedup 1.0000x reference)
#include <cuda_runtime.h>
#include <math.h>
#include <stdint.h>

#define B   2
#define T   2048
#define D   1024
#define NH  16
#define NKV 4
#define HD  64
#define GQ  4            // NH / NKV
#define EPSF 1.1920929e-07f
#define LOG2E 1.4426950408889634f
#define PSTR 12          // GEMM smem word stride (8 data + 4 pad) -> conflict-free frags
#define KSTR 36          // attn K plane stride (words): 36 mod 32 = 4 -> conflict-free
#define VSTR 68          // attn V plane stride (words): 68 mod 32 = 4 -> conflict-free

// ---------------- scratch (no allocations allowed) ----------------
__device__ float g_q[B*T*NH*HD];     // q projection -> normed/roped/gained q
__device__ float g_k[B*T*NKV*HD];    // k projection -> normed/roped k
__device__ float g_v[B*T*NKV*HD];    // v projection -> mixed v
__device__ float g_y[B*T*NH*HD];     // attention output (gate folded in)
__device__ float g_gate[B*T*NH];     // sigmoid gate per (b,t,head)

__device__ __forceinline__ float* scratch_buf(int id) {
    switch (id) {
        case 0: return g_q;
        case 1: return g_k;
        default: return g_v;
    }
}

// ---------------- bf16 helpers ----------------
__device__ __forceinline__ void mma_bf16(float* c, const uint32_t* a, const uint32_t* b) {
    asm volatile(
        "mma.sync.aligned.m16n8k16.row.col.f32.bf16.bf16.f32 "
        "{%0,%1,%2,%3}, {%4,%5,%6,%7}, {%8,%9}, {%0,%1,%2,%3};\n"
        : "+f"(c[0]), "+f"(c[1]), "+f"(c[2]), "+f"(c[3])
        : "r"(a[0]), "r"(a[1]), "r"(a[2]), "r"(a[3]), "r"(b[0]), "r"(b[1]));
}

// pack (x0,x1) -> bf16x2 hi word (low half = x0) and bf16x2 residual word
__device__ __forceinline__ void split2_pack(float x0, float x1, uint32_t& wh, uint32_t& wm) {
    asm("cvt.rn.bf16x2.f32 %0, %1, %2;" : "=r"(wh) : "f"(x1), "f"(x0));
    float h0 = __uint_as_float(wh << 16);
    float h1 = __uint_as_float(wh & 0xffff0000u);
    asm("cvt.rn.bf16x2.f32 %0, %1, %2;" : "=r"(wm) : "f"(x1 - h1), "f"(x0 - h0));
}

// ---------------- fused bf16-split GEMM ----------------
// job=0: QKV fused. grid.x: [0,8)=Q cols, [8,10)=K cols, [10,12)=V cols (+v epilogue).
// job=1: O projection (A = g_y, C = out).
// CTA 128x128, BK=16, 256 threads (8 warps 2x4), warp tile 64x32.
__global__ __launch_bounds__(256)
void gemm_bf16(const float* __restrict__ x,  const float* __restrict__ qw,
               const float* __restrict__ kw, const float* __restrict__ vw,
               const float* __restrict__ ow, const float* __restrict__ ve,
               const float* __restrict__ v0, const float* __restrict__ lam,
               float* __restrict__ out, float* __restrict__ raw_out, int job) {
    __shared__ uint32_t Ah[2][128*PSTR], Am[2][128*PSTR];
    __shared__ uint32_t Bh[2][128*PSTR], Bm[2][128*PSTR];

    const float* A; const float* W; float* C = nullptr; int N, n0; bool vjob = false;
    if (job == 0) {
        A = x;
        int bx = blockIdx.x;
        if (bx < 8)       { W = qw; C = g_q; N = NH*HD;  n0 = bx * 128; }
        else if (bx < 10) { W = kw; C = g_k; N = NKV*HD; n0 = (bx - 8) * 128; }
        else              { W = vw; C = g_v; N = NKV*HD; n0 = (bx - 10) * 128; vjob = true; }
    } else {
        A = g_y; W = ow; C = out; N = D; n0 = blockIdx.x * 128;
    }
    const int K = D;
    const int m0 = blockIdx.y * 128;

    const int tid  = threadIdx.x;
    const int lane = tid & 31;
    const int w    = tid >> 5;
    const int wm   = w & 1;
    const int wn   = w >> 1;
    const int tq   = lane >> 2;
    const int tr   = lane & 3;

    const int lrow = tid >> 1;           // 0..127
    const int lc8  = (tid & 1) * 8;
    const int lw   = (tid & 1) * 4;

    const float* aN = A + (size_t)(m0 + lrow) * K + lc8;
    const float* bN = W + (size_t)(n0 + lrow) * K + lc8;

    float c[16][4];
    #pragma unroll
    for (int i = 0; i < 16; i++)
        #pragma unroll
        for (int j = 0; j < 4; j++) c[i][j] = 0.f;

    {
        float4 a0 = *(const float4*)(aN);
        float4 a1 = *(const float4*)(aN + 4);
        float4 b0 = *(const float4*)(bN);
        float4 b1 = *(const float4*)(bN + 4);
        uint32_t h[4], m[4];
        split2_pack(a0.x, a0.y, h[0], m[0]); split2_pack(a0.z, a0.w, h[1], m[1]);
        split2_pack(a1.x, a1.y, h[2], m[2]); split2_pack(a1.z, a1.w, h[3], m[3]);
        *(uint4*)&Ah[0][lrow*PSTR + lw] = make_uint4(h[0], h[1], h[2], h[3]);
        *(uint4*)&Am[0][lrow*PSTR + lw] = make_uint4(m[0], m[1], m[2], m[3]);
        split2_pack(b0.x, b0.y, h[0], m[0]); split2_pack(b0.z, b0.w, h[1], m[1]);
        split2_pack(b1.x, b1.y, h[2], m[2]); split2_pack(b1.z, b1.w, h[3], m[3]);
        *(uint4*)&Bh[0][lrow*PSTR + lw] = make_uint4(h[0], h[1], h[2], h[3]);
        *(uint4*)&Bm[0][lrow*PSTR + lw] = make_uint4(m[0], m[1], m[2], m[3]);
    }
    __syncthreads();

    const int niter = K / 16;
    int cur = 0;
    for (int it = 0; it < niter; it++) {
        float4 pa0, pa1, pb0, pb1;
        const bool has_next = (it + 1 < niter);
        if (has_next) {
            int k0 = (it + 1) * 16;
            pa0 = *(const float4*)(aN + k0);
            pa1 = *(const float4*)(aN + k0 + 4);
            pb0 = *(const float4*)(bN + k0);
            pb1 = *(const float4*)(bN + k0 + 4);
        }

        const uint32_t* ah = Ah[cur]; const uint32_t* am = Am[cur];
        const uint32_t* bh = Bh[cur]; const uint32_t* bm = Bm[cur];

        uint32_t afh[4][4], afm[4][4], bfh[4][2], bfm[4][2];
        #pragma unroll
        for (int mi = 0; mi < 4; mi++) {
            int r = wm * 64 + mi * 16 + tq;
            afh[mi][0] = ah[r*PSTR + tr];     afh[mi][1] = ah[(r+8)*PSTR + tr];
            afh[mi][2] = ah[r*PSTR + tr + 4]; afh[mi][3] = ah[(r+8)*PSTR + tr + 4];
            afm[mi][0] = am[r*PSTR + tr];     afm[mi][1] = am[(r+8)*PSTR + tr];
            afm[mi][2] = am[r*PSTR + tr + 4]; afm[mi][3] = am[(r+8)*PSTR + tr + 4];
        }
        #pragma unroll
        for (int ni = 0; ni < 4; ni++) {
            int rn = wn * 32 + ni * 8 + tq;
            bfh[ni][0] = bh[rn*PSTR + tr]; bfh[ni][1] = bh[rn*PSTR + tr + 4];
            bfm[ni][0] = bm[rn*PSTR + tr]; bfm[ni][1] = bm[rn*PSTR + tr + 4];
        }
        #pragma unroll
        for (int mi = 0; mi < 4; mi++)
            #pragma unroll
            for (int ni = 0; ni < 4; ni++) {
                mma_bf16(c[mi*4+ni], afh[mi], bfh[ni]);
                mma_bf16(c[mi*4+ni], afh[mi], bfm[ni]);
                mma_bf16(c[mi*4+ni], afm[mi], bfh[ni]);
            }

        if (has_next) {
            int nxt = cur ^ 1;
            uint32_t h[4], m[4];
            split2_pack(pa0.x, pa0.y, h[0], m[0]); split2_pack(pa0.z, pa0.w, h[1], m[1]);
            split2_pack(pa1.x, pa1.y, h[2], m[2]); split2_pack(pa1.z, pa1.w, h[3], m[3]);
            *(uint4*)&Ah[nxt][lrow*PSTR + lw] = make_uint4(h[0], h[1], h[2], h[3]);
            *(uint4*)&Am[nxt][lrow*PSTR + lw] = make_uint4(m[0], m[1], m[2], m[3]);
            split2_pack(pb0.x, pb0.y, h[0], m[0]); split2_pack(pb0.z, pb0.w, h[1], m[1]);
            split2_pack(pb1.x, pb1.y, h[2], m[2]); split2_pack(pb1.z, pb1.w, h[3], m[3]);
            *(uint4*)&Bh[nxt][lrow*PSTR + lw] = make_uint4(h[0], h[1], h[2], h[3]);
            *(uint4*)&Bm[nxt][lrow*PSTR + lw] = make_uint4(m[0], m[1], m[2], m[3]);
            __syncthreads();
            cur = nxt;
        }
    }

    if (!vjob) {
        #pragma unroll
        for (int mi = 0; mi < 4; mi++)
            #pragma unroll
            for (int ni = 0; ni < 4; ni++) {
                int row = m0 + wm*64 + mi*16 + tq;
                int col = n0 + wn*32 + ni*8 + 2*tr;
                float* cp = c[mi*4+ni];
                *(float2*)(C + (size_t)row * N + col)       = make_float2(cp[0], cp[1]);
                *(float2*)(C + (size_t)(row + 8) * N + col) = make_float2(cp[2], cp[3]);
            }
    } else {
        const float l0 = lam[0], l1 = lam[1];
        #pragma unroll
        for (int mi = 0; mi < 4; mi++)
            #pragma unroll
            for (int ni = 0; ni < 4; ni++) {
                int row = m0 + wm*64 + mi*16 + tq;
                int col = n0 + wn*32 + ni*8 + 2*tr;
                float* cp = c[mi*4+ni];
                #pragma unroll
                for (int half = 0; half < 2; half++) {
                    size_t gi = (size_t)(row + half*8) * N + col;
                    float2 vee = *(const float2*)(ve + gi);
                    float2 v00 = *(const float2*)(v0 + gi);
                    float r0 = cp[half*2]   + vee.x;
                    float r1 = cp[half*2+1] + vee.y;
                    *(float2*)(raw_out + gi) = make_float2(r0, r1);
                    *(float2*)(C + gi) = make_float2(l0*v00.x + l1*r0, l0*v00.y + l1*r1);
                }
            }
    }
}

// ---------------- RMSNorm + RoPE (+ per-head gain) in place; one warp per row ----------------
// buf id resolved DEVICE-side (passing __device__ symbols from host is invalid).
__global__ void rmsnorm_rope(int buf, const float* __restrict__ gain, int H, double nb) {
    float* base = scratch_buf(buf);
    int row  = blockIdx.x * 8 + (threadIdx.x >> 5);
    int lane = threadIdx.x & 31;
    int t = (row / H) % T;
    int h = row % H;
    float* p = base + (size_t)row * HD;

    float a  = p[lane];
    float b2 = p[lane + 32];
    float ss = a*a + b2*b2;
    #pragma unroll
    for (int o = 16; o; o >>= 1) ss += __shfl_xor_sync(0xffffffffu, ss, o);
    float r = rsqrtf(ss * (1.0f/HD) + EPSF);
    a *= r; b2 *= r;

    float inv = (float)pow(nb, -(double)(2*lane) / (double)HD);
    float fr  = (float)t * inv;
    float c = (float)cos((double)fr);
    float s = (float)sin((double)fr);

    float o1 =  a*c + b2*s;
    float o2 = -a*s + b2*c;
    if (gain) { float gg = gain[h]; o1 *= gg; o2 *= gg; }
    p[lane]      = o1;
    p[lane + 32] = o2;
}

// ---------------- gate: sigmoid(x @ gate_w^T + gate_b), one block per (b,t) ----------------
__global__ void gate_kernel(const float* __restrict__ x, const float* __restrict__ gw,
                            const float* __restrict__ gb) {
    __shared__ float xs[D];
    int bt = blockIdx.x;
    for (int i = threadIdx.x; i < D; i += 512) xs[i] = x[(size_t)bt * D + i];
    __syncthreads();
    int h = threadIdx.x >> 5, lane = threadIdx.x & 31;
    const float* w = gw + (size_t)h * D;
    float s = 0.f;
    for (int i = lane; i < D; i += 32) s += xs[i] * w[i];
    #pragma unroll
    for (int o = 16; o; o >>= 1) s += __shfl_xor_sync(0xffffffffu, s, o);
    if (lane == 0) g_gate[bt * NH + h] = 1.0f / (1.0f + __expf(-(s + gb[h])));
}

// ---------------- bf16 tensor-core causal flash attention (pre-split smem planes) ----------------
// 4 warps, 64 q rows per CTA, 64-kv tiles. K packed along k, V packed along t:
// every B-fragment word is ONE 32-bit LDS, conflict-free.
__global__ __launch_bounds__(128)
void attn_bf16() {
    __shared__ uint32_t Kh[64*KSTR], Km[64*KSTR];   // [key n][k/2]
    __shared__ uint32_t Vh[32*VSTR], Vm[32*VSTR];   // [t/2][d]

    const int qt = (int)gridDim.x - 1 - (int)blockIdx.x;   // heavy tiles first
    const int h = blockIdx.y, b = blockIdx.z;
    const int kv = h / GQ;
    const int tid = threadIdx.x;
    const int w = tid >> 5, lane = tid & 31;
    const int tq = lane >> 2, tr = lane & 3;
    const int r0 = w * 16 + tq;      // warp-local q row (and +8)

    // ---- persistent Q fragments straight from global (L2-cached) ----
    uint32_t qh[4][4], qm[4][4];
    {
        const float* qa = g_q + ((size_t)(b*T + qt*64 + r0) * NH + h) * HD;
        const float* qb = qa + (size_t)8 * NH * HD;
        #pragma unroll
        for (int kb = 0; kb < 4; kb++) {
            int k0 = kb*16 + 2*tr;
            float2 a0 = *(const float2*)(qa + k0);
            float2 a1 = *(const float2*)(qb + k0);
            float2 a2 = *(const float2*)(qa + k0 + 8);
            float2 a3 = *(const float2*)(qb + k0 + 8);
            split2_pack(a0.x, a0.y, qh[kb][0], qm[kb][0]);
            split2_pack(a1.x, a1.y, qh[kb][1], qm[kb][1]);
            split2_pack(a2.x, a2.y, qh[kb][2], qm[kb][2]);
            split2_pack(a3.x, a3.y, qh[kb][3], qm[kb][3]);
        }
    }

    float o[8][4];
    #pragma unroll
    for (int ni = 0; ni < 8; ni++)
        #pragma unroll
        for (int j = 0; j < 4; j++) o[ni][j] = 0.f;
    float m0r = -1e30f, m1r = -1e30f, l0r = 0.f, l1r = 0.f;

    for (int kt = 0; kt <= qt; kt++) {
        const int t0 = kt * 64;
        __syncthreads();
        // K: 64 rows x 8 chunks (8 floats) -> packed along k
        #pragma unroll
        for (int ci = 0; ci < 4; ci++) {
            int i = tid + ci * 128;
            int r = i >> 3, j = i & 7;
            const float* src = g_k + ((size_t)(b*T + t0 + r) * NKV + kv) * HD + j * 8;
            float4 x0 = *(const float4*)(src);
            float4 x1 = *(const float4*)(src + 4);
            uint32_t h4[4], m4[4];
            split2_pack(x0.x, x0.y, h4[0], m4[0]);
            split2_pack(x0.z, x0.w, h4[1], m4[1]);
            split2_pack(x1.x, x1.y, h4[2], m4[2]);
            split2_pack(x1.z, x1.w, h4[3], m4[3]);
            *(uint4*)&Kh[r*KSTR + j*4] = make_uint4(h4[0], h4[1], h4[2], h4[3]);
            *(uint4*)&Km[r*KSTR + j*4] = make_uint4(m4[0], m4[1], m4[2], m4[3]);
        }
        // V: 32 row-pairs x 16 chunks (4 d) -> packed along t
        #pragma unroll
        for (int ci = 0; ci < 4; ci++) {
            int i = tid + ci * 128;
            int tp = i >> 4, d4 = (i & 15) * 4;
            const float* s0 = g_v + ((size_t)(b*T + t0 + 2*tp)     * NKV + kv) * HD + d4;
            const float* s1 = g_v + ((size_t)(b*T + t0 + 2*tp + 1) * NKV + kv) * HD + d4;
            float4 x0 = *(const float4*)s0;
            float4 x1 = *(const float4*)s1;
            uint32_t h4[4], m4[4];
            split2_pack(x0.x, x1.x, h4[0], m4[0]);
            split2_pack(x0.y, x1.y, h4[1], m4[1]);
            split2_pack(x0.z, x1.z, h4[2], m4[2]);
            split2_pack(x0.w, x1.w, h4[3], m4[3]);
            *(uint4*)&Vh[tp*VSTR + d4] = make_uint4(h4[0], h4[1], h4[2], h4[3]);
            *(uint4*)&Vm[tp*VSTR + d4] = make_uint4(m4[0], m4[1], m4[2], m4[3]);
        }
        __syncthreads();

        // ---- S = Q @ K^T ----
        float s[8][4];
        #pragma unroll
        for (int ni = 0; ni < 8; ni++) {
            s[ni][0] = s[ni][1] = s[ni][2] = s[ni][3] = 0.f;
            const int kn = (ni*8 + tq) * KSTR;
            #pragma unroll
            for (int kb = 0; kb < 4; kb++) {
                uint32_t bh[2], bm[2];
                bh[0] = Kh[kn + kb*8 + tr];     bh[1] = Kh[kn + kb*8 + tr + 4];
                bm[0] = Km[kn + kb*8 + tr];     bm[1] = Km[kn + kb*8 + tr + 4];
                mma_bf16(s[ni], qh[kb], bh);
                mma_bf16(s[ni], qh[kb], bm);
                mma_bf16(s[ni], qm[kb], bh);
            }
        }

        // ---- causal mask (diagonal tile only) ----
        const int rowa = qt*64 + r0, rowb = rowa + 8;
        if (kt == qt) {
            #pragma unroll
            for (int ni = 0; ni < 8; ni++) {
                int col = t0 + ni*8 + 2*tr;
                if (col     > rowa) s[ni][0] = -1e30f;
                if (col + 1 > rowa) s[ni][1] = -1e30f;
                if (col     > rowb) s[ni][2] = -1e30f;
                if (col + 1 > rowb) s[ni][3] = -1e30f;
            }
        }

        // ---- online softmax (logits = s * 0.125) ----
        const float SC = 0.125f;
        float mx0 = -1e30f, mx1 = -1e30f;
        #pragma unroll
        for (int ni = 0; ni < 8; ni++) {
            mx0 = fmaxf(mx0, fmaxf(s[ni][0], s[ni][1]));
            mx1 = fmaxf(mx1, fmaxf(s[ni][2], s[ni][3]));
        }
        mx0 = fmaxf(mx0, __shfl_xor_sync(0xffffffffu, mx0, 1));
        mx0 = fmaxf(mx0, __shfl_xor_sync(0xffffffffu, mx0, 2));
        mx1 = fmaxf(mx1, __shfl_xor_sync(0xffffffffu, mx1, 1));
        mx1 = fmaxf(mx1, __shfl_xor_sync(0xffffffffu, mx1, 2));
        float mn0 = fmaxf(m0r, mx0 * SC);
        float mn1 = fmaxf(m1r, mx1 * SC);
        float al0 = exp2f((m0r - mn0) * LOG2E);
        float al1 = exp2f((m1r - mn1) * LOG2E);
        m0r = mn0; m1r = mn1;

        float sum0 = 0.f, sum1 = 0.f;
        #pragma unroll
        for (int ni = 0; ni < 8; ni++) {
            float p0 = exp2f((s[ni][0] * SC - mn0) * LOG2E);
            float p1 = exp2f((s[ni][1] * SC - mn0) * LOG2E);
            float p2 = exp2f((s[ni][2] * SC - mn1) * LOG2E);
            float p3 = exp2f((s[ni][3] * SC - mn1) * LOG2E);
            s[ni][0] = p0; s[ni][1] = p1; s[ni][2] = p2; s[ni][3] = p3;
            sum0 += p0 + p1; sum1 += p2 + p3;
            o[ni][0] *= al0; o[ni][1] *= al0; o[ni][2] *= al1; o[ni][3] *= al1;
        }
        sum0 += __shfl_xor_sync(0xffffffffu, sum0, 1);
        sum0 += __shfl_xor_sync(0xffffffffu, sum0, 2);
        sum1 += __shfl_xor_sync(0xffffffffu, sum1, 1);
        sum1 += __shfl_xor_sync(0xffffffffu, sum1, 2);
        l0r = l0r * al0 + sum0;
        l1r = l1r * al1 + sum1;

        // ---- O += P @ V; A-fragments straight from S C-fragments, V words single LDS ----
        #pragma unroll
        for (int c0 = 0; c0 < 4; c0++) {
            uint32_t ph[4], pm[4];
            split2_pack(s[2*c0][0],   s[2*c0][1],   ph[0], pm[0]);
            split2_pack(s[2*c0][2],   s[2*c0][3],   ph[1], pm[1]);
            split2_pack(s[2*c0+1][0], s[2*c0+1][1], ph[2], pm[2]);
            split2_pack(s[2*c0+1][2], s[2*c0+1][3], ph[3], pm[3]);
            const int ra = (c0*8 + tr) * VSTR;
            #pragma unroll
            for (int ni = 0; ni < 8; ni++) {
                const int dd = ni*8 + tq;
                uint32_t vh[2], vm[2];
                vh[0] = Vh[ra + dd];           vh[1] = Vh[ra + 4*VSTR + dd];
                vm[0] = Vm[ra + dd];           vm[1] = Vm[ra + 4*VSTR + dd];
                mma_bf16(o[ni], ph, vh);
                mma_bf16(o[ni], ph, vm);
                mma_bf16(o[ni], pm, vh);
            }
        }
    }

    // ---- epilogue: y = o / l * gate ----
    const int rowa = qt*64 + r0, rowb = rowa + 8;
    float g0 = g_gate[(b*T + rowa) * NH + h] / l0r;
    float g1 = g_gate[(b*T + rowb) * NH + h] / l1r;
    #pragma unroll
    for (int ni = 0; ni < 8; ni++) {
        int col = ni*8 + 2*tr;
        size_t ba = ((size_t)(b*T + rowa) * NH + h) * HD + col;
        size_t bb = ((size_t)(b*T + rowb) * NH + h) * HD + col;
        *(float2*)(g_y + ba) = make_float2(o[ni][0] * g0, o[ni][1] * g0);
        *(float2*)(g_y + bb) = make_float2(o[ni][2] * g1, o[ni][3] * g1);
    }
}

// ---------------- launch ----------------
extern "C" void kernel_launch(void* const* d_in, const int* in_sizes, int n_in,
                              void* d_out, int out_size) {
    (void)in_sizes; (void)n_in; (void)out_size;
    const float* x  = (const float*)d_in[0];
    const float* qw = (const float*)d_in[1];
    const float* kw = (const float*)d_in[2];
    const float* vw = (const float*)d_in[3];
    const float* ow = (const float*)d_in[4];
    const float* ve = (const float*)d_in[5];
    const float* v0 = (const float*)d_in[6];
    const float* qg = (const float*)d_in[7];
    const float* vl = (const float*)d_in[8];
    const float* gw = (const float*)d_in[9];
    const float* gb = (const float*)d_in[10];

    float* out     = (float*)d_out;
    float* raw_out = out + (size_t)B * T * D;     // second output: raw_v

    // NTK-scaled base: T=2048 > TSL=1024
    const double nb = 10000.0 * pow((double)T / 1024.0, 64.0 / 62.0);

    // fused QKV projections (+ V epilogue inside)
    gemm_bf16<<<dim3(12, (B*T)/128), 256>>>(x, qw, kw, vw, nullptr, ve, v0, vl,
                                            nullptr, raw_out, 0);

    // rmsnorm + rope (+ q gain); buffers resolved device-side by id
    rmsnorm_rope<<<(B*T*NH)/8,  256>>>(0, qg,      NH,  nb);
    rmsnorm_rope<<<(B*T*NKV)/8, 256>>>(1, nullptr, NKV, nb);

    // gate
    gate_kernel<<<B*T, 512>>>(x, gw, gb);

    // bf16 tensor-core attention (gate folded into epilogue)
    attn_bf16<<<dim3(T/64, NH, B), 128>>>();

    // output projection
    gemm_bf16<<<dim3(D/128, (B*T)/128), 256>>>(nullptr, nullptr, nullptr, nullptr, ow,
                                               nullptr, nullptr, nullptr, out, nullptr, 1);
}

// round 9
// speedup vs baseline: 1.5523x; 1.5523x over previous
#include <cuda_runtime.h>
#include <math.h>
#include <stdint.h>

#define B   2
#define T   2048
#define D   1024
#define NH  16
#define NKV 4
#define HD  64
#define GQ  4            // NH / NKV
#define EPSF 1.1920929e-07f
#define LOG2E 1.4426950408889634f
#define PSTR 12          // GEMM smem word stride (8 data + 4 pad) -> conflict-free frags

// ---------------- scratch (no allocations allowed) ----------------
__device__ float g_q[B*T*NH*HD];     // q projection -> normed/roped/gained q
__device__ float g_k[B*T*NKV*HD];    // k projection -> normed/roped k
__device__ float g_v[B*T*NKV*HD];    // v projection (mixed in epilogue)
__device__ float g_y[B*T*NH*HD];     // attention output (gate folded in)
__device__ float g_gate[B*T*NH];     // sigmoid gate per (b,t,head)

__device__ __forceinline__ float* scratch_buf(int id) {
    switch (id) {
        case 0: return g_q;
        case 1: return g_k;
        default: return g_v;
    }
}

// ---------------- bf16 helpers ----------------
__device__ __forceinline__ void mma_bf16(float* c, const uint32_t* a, const uint32_t* b) {
    asm volatile(
        "mma.sync.aligned.m16n8k16.row.col.f32.bf16.bf16.f32 "
        "{%0,%1,%2,%3}, {%4,%5,%6,%7}, {%8,%9}, {%0,%1,%2,%3};\n"
        : "+f"(c[0]), "+f"(c[1]), "+f"(c[2]), "+f"(c[3])
        : "r"(a[0]), "r"(a[1]), "r"(a[2]), "r"(a[3]), "r"(b[0]), "r"(b[1]));
}

// pack (x0,x1) -> bf16x2 hi word (low half = x0) and bf16x2 residual word
__device__ __forceinline__ void split2_pack(float x0, float x1, uint32_t& wh, uint32_t& wm) {
    asm("cvt.rn.bf16x2.f32 %0, %1, %2;" : "=r"(wh) : "f"(x1), "f"(x0));
    float h0 = __uint_as_float(wh << 16);
    float h1 = __uint_as_float(wh & 0xffff0000u);
    asm("cvt.rn.bf16x2.f32 %0, %1, %2;" : "=r"(wm) : "f"(x1 - h1), "f"(x0 - h0));
}

// ---------------- fused bf16-split GEMM ----------------
// job=0: QKV fused. grid.x: [0,8)=Q cols, [8,10)=K cols, [10,12)=V cols (+v epilogue).
// job=1: O projection (A = g_y, C = out).
// CTA 128x128, BK=16, 256 threads (8 warps 2x4), warp tile 64x32.
__global__ __launch_bounds__(256)
void gemm_bf16(const float* __restrict__ x,  const float* __restrict__ qw,
               const float* __restrict__ kw, const float* __restrict__ vw,
               const float* __restrict__ ow, const float* __restrict__ ve,
               const float* __restrict__ v0, const float* __restrict__ lam,
               float* __restrict__ out, float* __restrict__ raw_out, int job) {
    __shared__ uint32_t Ah[2][128*PSTR], Am[2][128*PSTR];
    __shared__ uint32_t Bh[2][128*PSTR], Bm[2][128*PSTR];

    const float* A; const float* W; float* C = nullptr; int N, n0; bool vjob = false;
    if (job == 0) {
        A = x;
        int bx = blockIdx.x;
        if (bx < 8)       { W = qw; C = g_q; N = NH*HD;  n0 = bx * 128; }
        else if (bx < 10) { W = kw; C = g_k; N = NKV*HD; n0 = (bx - 8) * 128; }
        else              { W = vw; C = g_v; N = NKV*HD; n0 = (bx - 10) * 128; vjob = true; }
    } else {
        A = g_y; W = ow; C = out; N = D; n0 = blockIdx.x * 128;
    }
    const int K = D;
    const int m0 = blockIdx.y * 128;

    const int tid  = threadIdx.x;
    const int lane = tid & 31;
    const int w    = tid >> 5;
    const int wm   = w & 1;
    const int wn   = w >> 1;
    const int tq   = lane >> 2;
    const int tr   = lane & 3;

    const int lrow = tid >> 1;           // 0..127
    const int lc8  = (tid & 1) * 8;
    const int lw   = (tid & 1) * 4;

    const float* aN = A + (size_t)(m0 + lrow) * K + lc8;
    const float* bN = W + (size_t)(n0 + lrow) * K + lc8;

    float c[16][4];
    #pragma unroll
    for (int i = 0; i < 16; i++)
        #pragma unroll
        for (int j = 0; j < 4; j++) c[i][j] = 0.f;

    {
        float4 a0 = *(const float4*)(aN);
        float4 a1 = *(const float4*)(aN + 4);
        float4 b0 = *(const float4*)(bN);
        float4 b1 = *(const float4*)(bN + 4);
        uint32_t h[4], m[4];
        split2_pack(a0.x, a0.y, h[0], m[0]); split2_pack(a0.z, a0.w, h[1], m[1]);
        split2_pack(a1.x, a1.y, h[2], m[2]); split2_pack(a1.z, a1.w, h[3], m[3]);
        *(uint4*)&Ah[0][lrow*PSTR + lw] = make_uint4(h[0], h[1], h[2], h[3]);
        *(uint4*)&Am[0][lrow*PSTR + lw] = make_uint4(m[0], m[1], m[2], m[3]);
        split2_pack(b0.x, b0.y, h[0], m[0]); split2_pack(b0.z, b0.w, h[1], m[1]);
        split2_pack(b1.x, b1.y, h[2], m[2]); split2_pack(b1.z, b1.w, h[3], m[3]);
        *(uint4*)&Bh[0][lrow*PSTR + lw] = make_uint4(h[0], h[1], h[2], h[3]);
        *(uint4*)&Bm[0][lrow*PSTR + lw] = make_uint4(m[0], m[1], m[2], m[3]);
    }
    __syncthreads();

    const int niter = K / 16;
    int cur = 0;
    for (int it = 0; it < niter; it++) {
        float4 pa0, pa1, pb0, pb1;
        const bool has_next = (it + 1 < niter);
        if (has_next) {
            int k0 = (it + 1) * 16;
            pa0 = *(const float4*)(aN + k0);
            pa1 = *(const float4*)(aN + k0 + 4);
            pb0 = *(const float4*)(bN + k0);
            pb1 = *(const float4*)(bN + k0 + 4);
        }

        const uint32_t* ah = Ah[cur]; const uint32_t* am = Am[cur];
        const uint32_t* bh = Bh[cur]; const uint32_t* bm = Bm[cur];

        uint32_t afh[4][4], afm[4][4], bfh[4][2], bfm[4][2];
        #pragma unroll
        for (int mi = 0; mi < 4; mi++) {
            int r = wm * 64 + mi * 16 + tq;
            afh[mi][0] = ah[r*PSTR + tr];     afh[mi][1] = ah[(r+8)*PSTR + tr];
            afh[mi][2] = ah[r*PSTR + tr + 4]; afh[mi][3] = ah[(r+8)*PSTR + tr + 4];
            afm[mi][0] = am[r*PSTR + tr];     afm[mi][1] = am[(r+8)*PSTR + tr];
            afm[mi][2] = am[r*PSTR + tr + 4]; afm[mi][3] = am[(r+8)*PSTR + tr + 4];
        }
        #pragma unroll
        for (int ni = 0; ni < 4; ni++) {
            int rn = wn * 32 + ni * 8 + tq;
            bfh[ni][0] = bh[rn*PSTR + tr]; bfh[ni][1] = bh[rn*PSTR + tr + 4];
            bfm[ni][0] = bm[rn*PSTR + tr]; bfm[ni][1] = bm[rn*PSTR + tr + 4];
        }
        #pragma unroll
        for (int mi = 0; mi < 4; mi++)
            #pragma unroll
            for (int ni = 0; ni < 4; ni++) {
                mma_bf16(c[mi*4+ni], afh[mi], bfh[ni]);
                mma_bf16(c[mi*4+ni], afh[mi], bfm[ni]);
                mma_bf16(c[mi*4+ni], afm[mi], bfh[ni]);
            }

        if (has_next) {
            int nxt = cur ^ 1;
            uint32_t h[4], m[4];
            split2_pack(pa0.x, pa0.y, h[0], m[0]); split2_pack(pa0.z, pa0.w, h[1], m[1]);
            split2_pack(pa1.x, pa1.y, h[2], m[2]); split2_pack(pa1.z, pa1.w, h[3], m[3]);
            *(uint4*)&Ah[nxt][lrow*PSTR + lw] = make_uint4(h[0], h[1], h[2], h[3]);
            *(uint4*)&Am[nxt][lrow*PSTR + lw] = make_uint4(m[0], m[1], m[2], m[3]);
            split2_pack(pb0.x, pb0.y, h[0], m[0]); split2_pack(pb0.z, pb0.w, h[1], m[1]);
            split2_pack(pb1.x, pb1.y, h[2], m[2]); split2_pack(pb1.z, pb1.w, h[3], m[3]);
            *(uint4*)&Bh[nxt][lrow*PSTR + lw] = make_uint4(h[0], h[1], h[2], h[3]);
            *(uint4*)&Bm[nxt][lrow*PSTR + lw] = make_uint4(m[0], m[1], m[2], m[3]);
            __syncthreads();
            cur = nxt;
        }
    }

    if (!vjob) {
        #pragma unroll
        for (int mi = 0; mi < 4; mi++)
            #pragma unroll
            for (int ni = 0; ni < 4; ni++) {
                int row = m0 + wm*64 + mi*16 + tq;
                int col = n0 + wn*32 + ni*8 + 2*tr;
                float* cp = c[mi*4+ni];
                *(float2*)(C + (size_t)row * N + col)       = make_float2(cp[0], cp[1]);
                *(float2*)(C + (size_t)(row + 8) * N + col) = make_float2(cp[2], cp[3]);
            }
    } else {
        const float l0 = lam[0], l1 = lam[1];
        #pragma unroll
        for (int mi = 0; mi < 4; mi++)
            #pragma unroll
            for (int ni = 0; ni < 4; ni++) {
                int row = m0 + wm*64 + mi*16 + tq;
                int col = n0 + wn*32 + ni*8 + 2*tr;
                float* cp = c[mi*4+ni];
                #pragma unroll
                for (int half = 0; half < 2; half++) {
                    size_t gi = (size_t)(row + half*8) * N + col;
                    float2 vee = *(const float2*)(ve + gi);
                    float2 v00 = *(const float2*)(v0 + gi);
                    float r0 = cp[half*2]   + vee.x;
                    float r1 = cp[half*2+1] + vee.y;
                    *(float2*)(raw_out + gi) = make_float2(r0, r1);
                    *(float2*)(C + gi) = make_float2(l0*v00.x + l1*r0, l0*v00.y + l1*r1);
                }
            }
    }
}

// ---------------- RMSNorm + RoPE (+ per-head gain) in place; one warp per row ----------------
__global__ void rmsnorm_rope(int buf, const float* __restrict__ gain, int H, double nb) {
    float* base = scratch_buf(buf);
    int row  = blockIdx.x * 8 + (threadIdx.x >> 5);
    int lane = threadIdx.x & 31;
    int t = (row / H) % T;
    int h = row % H;
    float* p = base + (size_t)row * HD;

    float a  = p[lane];
    float b2 = p[lane + 32];
    float ss = a*a + b2*b2;
    #pragma unroll
    for (int o = 16; o; o >>= 1) ss += __shfl_xor_sync(0xffffffffu, ss, o);
    float r = rsqrtf(ss * (1.0f/HD) + EPSF);
    a *= r; b2 *= r;

    float inv = (float)pow(nb, -(double)(2*lane) / (double)HD);
    float fr  = (float)t * inv;
    float c = (float)cos((double)fr);
    float s = (float)sin((double)fr);

    float o1 =  a*c + b2*s;
    float o2 = -a*s + b2*c;
    if (gain) { float gg = gain[h]; o1 *= gg; o2 *= gg; }
    p[lane]      = o1;
    p[lane + 32] = o2;
}

// ---------------- gate: sigmoid(x @ gate_w^T + gate_b), one block per (b,t) ----------------
__global__ void gate_kernel(const float* __restrict__ x, const float* __restrict__ gw,
                            const float* __restrict__ gb) {
    __shared__ float xs[D];
    int bt = blockIdx.x;
    for (int i = threadIdx.x; i < D; i += 512) xs[i] = x[(size_t)bt * D + i];
    __syncthreads();
    int h = threadIdx.x >> 5, lane = threadIdx.x & 31;
    const float* w = gw + (size_t)h * D;
    float s = 0.f;
    for (int i = lane; i < D; i += 32) s += xs[i] * w[i];
    #pragma unroll
    for (int o = 16; o; o >>= 1) s += __shfl_xor_sync(0xffffffffu, s, o);
    if (lane == 0) g_gate[bt * NH + h] = 1.0f / (1.0f + __expf(-(s + gb[h])));
}

// ---------------- bf16 tensor-core causal flash attention (round-4 proven version) ----------------
// 4 warps, 64 q rows per CTA (16/warp), 64-kv tiles. bf16 split MMAs, splits interleaved
// with MMAs (dual-issue vs tensor pipe); A-fragments for P·V straight from S C-fragments.
__global__ __launch_bounds__(128)
void attn_bf16() {
    __shared__ float Ks[64][68];
    __shared__ float Vs[64][68];

    const int qt = (int)gridDim.x - 1 - (int)blockIdx.x;   // heavy tiles first
    const int h = blockIdx.y, b = blockIdx.z;
    const int kv = h / GQ;
    const int tid = threadIdx.x;
    const int w = tid >> 5, lane = tid & 31;
    const int tq = lane >> 2, tr = lane & 3;
    const int r0 = w * 16 + tq;      // warp-local q row (and +8)

    // ---- stage Q tile, build persistent hi/mid Q fragments (4 k16 blocks) ----
    for (int i = tid; i < 64 * 16; i += 128) {
        int r = i >> 4, c4 = (i & 15) * 4;
        float4 v = *(const float4*)(g_q + ((size_t)(b*T + qt*64 + r) * NH + h) * HD + c4);
        Ks[r][c4] = v.x; Ks[r][c4+1] = v.y; Ks[r][c4+2] = v.z; Ks[r][c4+3] = v.w;
    }
    __syncthreads();

    uint32_t qh[4][4], qm[4][4];
    #pragma unroll
    for (int kb = 0; kb < 4; kb++) {
        int k0 = kb*16 + 2*tr;
        split2_pack(Ks[r0][k0],       Ks[r0][k0+1],       qh[kb][0], qm[kb][0]);
        split2_pack(Ks[r0+8][k0],     Ks[r0+8][k0+1],     qh[kb][1], qm[kb][1]);
        split2_pack(Ks[r0][k0+8],     Ks[r0][k0+9],       qh[kb][2], qm[kb][2]);
        split2_pack(Ks[r0+8][k0+8],   Ks[r0+8][k0+9],     qh[kb][3], qm[kb][3]);
    }
    __syncthreads();

    float o[8][4];
    #pragma unroll
    for (int ni = 0; ni < 8; ni++)
        #pragma unroll
        for (int j = 0; j < 4; j++) o[ni][j] = 0.f;
    float m0r = -1e30f, m1r = -1e30f, l0r = 0.f, l1r = 0.f;

    for (int kt = 0; kt <= qt; kt++) {
        const int t0 = kt * 64;
        __syncthreads();
        for (int i = tid; i < 64 * 16; i += 128) {
            int r = i >> 4, c4 = (i & 15) * 4;
            size_t base = ((size_t)(b*T + t0 + r) * NKV + kv) * HD + c4;
            float4 kk = *(const float4*)(g_k + base);
            float4 vv = *(const float4*)(g_v + base);
            Ks[r][c4] = kk.x; Ks[r][c4+1] = kk.y; Ks[r][c4+2] = kk.z; Ks[r][c4+3] = kk.w;
            Vs[r][c4] = vv.x; Vs[r][c4+1] = vv.y; Vs[r][c4+2] = vv.z; Vs[r][c4+3] = vv.w;
        }
        __syncthreads();

        // ---- S = Q @ K^T (bf16 split) ----
        float s[8][4];
        #pragma unroll
        for (int ni = 0; ni < 8; ni++) {
            s[ni][0] = s[ni][1] = s[ni][2] = s[ni][3] = 0.f;
            const int kn = ni*8 + tq;
            #pragma unroll
            for (int kb = 0; kb < 4; kb++) {
                int k0 = kb*16 + 2*tr;
                uint32_t bh[2], bm[2];
                split2_pack(Ks[kn][k0],   Ks[kn][k0+1], bh[0], bm[0]);
                split2_pack(Ks[kn][k0+8], Ks[kn][k0+9], bh[1], bm[1]);
                mma_bf16(s[ni], qh[kb], bh);
                mma_bf16(s[ni], qh[kb], bm);
                mma_bf16(s[ni], qm[kb], bh);
            }
        }

        // ---- causal mask (diagonal tile only) ----
        const int rowa = qt*64 + r0, rowb = rowa + 8;
        if (kt == qt) {
            #pragma unroll
            for (int ni = 0; ni < 8; ni++) {
                int col = t0 + ni*8 + 2*tr;
                if (col     > rowa) s[ni][0] = -1e30f;
                if (col + 1 > rowa) s[ni][1] = -1e30f;
                if (col     > rowb) s[ni][2] = -1e30f;
                if (col + 1 > rowb) s[ni][3] = -1e30f;
            }
        }

        // ---- online softmax (logits = s * 0.125) ----
        const float SC = 0.125f;
        float mx0 = -1e30f, mx1 = -1e30f;
        #pragma unroll
        for (int ni = 0; ni < 8; ni++) {
            mx0 = fmaxf(mx0, fmaxf(s[ni][0], s[ni][1]));
            mx1 = fmaxf(mx1, fmaxf(s[ni][2], s[ni][3]));
        }
        mx0 = fmaxf(mx0, __shfl_xor_sync(0xffffffffu, mx0, 1));
        mx0 = fmaxf(mx0, __shfl_xor_sync(0xffffffffu, mx0, 2));
        mx1 = fmaxf(mx1, __shfl_xor_sync(0xffffffffu, mx1, 1));
        mx1 = fmaxf(mx1, __shfl_xor_sync(0xffffffffu, mx1, 2));
        float mn0 = fmaxf(m0r, mx0 * SC);
        float mn1 = fmaxf(m1r, mx1 * SC);
        float al0 = exp2f((m0r - mn0) * LOG2E);
        float al1 = exp2f((m1r - mn1) * LOG2E);
        m0r = mn0; m1r = mn1;

        float sum0 = 0.f, sum1 = 0.f;
        #pragma unroll
        for (int ni = 0; ni < 8; ni++) {
            float p0 = exp2f((s[ni][0] * SC - mn0) * LOG2E);
            float p1 = exp2f((s[ni][1] * SC - mn0) * LOG2E);
            float p2 = exp2f((s[ni][2] * SC - mn1) * LOG2E);
            float p3 = exp2f((s[ni][3] * SC - mn1) * LOG2E);
            s[ni][0] = p0; s[ni][1] = p1; s[ni][2] = p2; s[ni][3] = p3;
            sum0 += p0 + p1; sum1 += p2 + p3;
            o[ni][0] *= al0; o[ni][1] *= al0; o[ni][2] *= al1; o[ni][3] *= al1;
        }
        sum0 += __shfl_xor_sync(0xffffffffu, sum0, 1);
        sum0 += __shfl_xor_sync(0xffffffffu, sum0, 2);
        sum1 += __shfl_xor_sync(0xffffffffu, sum1, 1);
        sum1 += __shfl_xor_sync(0xffffffffu, sum1, 2);
        l0r = l0r * al0 + sum0;
        l1r = l1r * al1 + sum1;

        // ---- O += P @ V (bf16 split); A-fragments straight from S C-fragments ----
        #pragma unroll
        for (int c0 = 0; c0 < 4; c0++) {
            uint32_t ph[4], pm[4];
            split2_pack(s[2*c0][0],   s[2*c0][1],   ph[0], pm[0]);
            split2_pack(s[2*c0][2],   s[2*c0][3],   ph[1], pm[1]);
            split2_pack(s[2*c0+1][0], s[2*c0+1][1], ph[2], pm[2]);
            split2_pack(s[2*c0+1][2], s[2*c0+1][3], ph[3], pm[3]);
            const int ta = c0*16 + 2*tr;
            #pragma unroll
            for (int ni = 0; ni < 8; ni++) {
                const int dd = ni*8 + tq;
                uint32_t vh[2], vm[2];
                split2_pack(Vs[ta][dd],   Vs[ta+1][dd], vh[0], vm[0]);
                split2_pack(Vs[ta+8][dd], Vs[ta+9][dd], vh[1], vm[1]);
                mma_bf16(o[ni], ph, vh);
                mma_bf16(o[ni], ph, vm);
                mma_bf16(o[ni], pm, vh);
            }
        }
    }

    // ---- epilogue: y = o / l * gate ----
    const int rowa = qt*64 + r0, rowb = rowa + 8;
    float g0 = g_gate[(b*T + rowa) * NH + h] / l0r;
    float g1 = g_gate[(b*T + rowb) * NH + h] / l1r;
    #pragma unroll
    for (int ni = 0; ni < 8; ni++) {
        int col = ni*8 + 2*tr;
        size_t ba = ((size_t)(b*T + rowa) * NH + h) * HD + col;
        size_t bb = ((size_t)(b*T + rowb) * NH + h) * HD + col;
        *(float2*)(g_y + ba) = make_float2(o[ni][0] * g0, o[ni][1] * g0);
        *(float2*)(g_y + bb) = make_float2(o[ni][2] * g1, o[ni][3] * g1);
    }
}

// ---------------- launch ----------------
extern "C" void kernel_launch(void* const* d_in, const int* in_sizes, int n_in,
                              void* d_out, int out_size) {
    (void)in_sizes; (void)n_in; (void)out_size;
    const float* x  = (const float*)d_in[0];
    const float* qw = (const float*)d_in[1];
    const float* kw = (const float*)d_in[2];
    const float* vw = (const float*)d_in[3];
    const float* ow = (const float*)d_in[4];
    const float* ve = (const float*)d_in[5];
    const float* v0 = (const float*)d_in[6];
    const float* qg = (const float*)d_in[7];
    const float* vl = (const float*)d_in[8];
    const float* gw = (const float*)d_in[9];
    const float* gb = (const float*)d_in[10];

    float* out     = (float*)d_out;
    float* raw_out = out + (size_t)B * T * D;     // second output: raw_v

    // NTK-scaled base: T=2048 > TSL=1024
    const double nb = 10000.0 * pow((double)T / 1024.0, 64.0 / 62.0);

    // fused QKV projections (+ V epilogue folded into V tiles)
    gemm_bf16<<<dim3(12, (B*T)/128), 256>>>(x, qw, kw, vw, nullptr, ve, v0, vl,
                                            nullptr, raw_out, 0);

    // rmsnorm + rope (+ q gain); buffers resolved device-side by id
    rmsnorm_rope<<<(B*T*NH)/8,  256>>>(0, qg,      NH,  nb);
    rmsnorm_rope<<<(B*T*NKV)/8, 256>>>(1, nullptr, NKV, nb);

    // gate
    gate_kernel<<<B*T, 512>>>(x, gw, gb);

    // bf16 tensor-core attention (gate folded into epilogue)
    attn_bf16<<<dim3(T/64, NH, B), 128>>>();

    // output projection
    gemm_bf16<<<dim3(D/128, (B*T)/128), 256>>>(nullptr, nullptr, nullptr, nullptr, ow,
                                               nullptr, nullptr, nullptr, out, nullptr, 1);
}

// round 10
// speedup vs baseline: 1.6376x; 1.0550x over previous
#include <cuda_runtime.h>
#include <math.h>
#include <stdint.h>

#define B   2
#define T   2048
#define D   1024
#define NH  16
#define NKV 4
#define HD  64
#define GQ  4            // NH / NKV
#define EPSF 1.1920929e-07f
#define LOG2E 1.4426950408889634f
#define PSTR 12          // GEMM smem word stride (8 data + 4 pad) -> conflict-free frags
#define KSTR 36          // attn K plane stride: 36 mod 32 = 4 -> banks 4tq+tr (perm)
#define VSTR 72          // attn V plane stride: 72 mod 32 = 8 -> banks 8tr+tq (perm)

// ---------------- scratch (no allocations allowed) ----------------
__device__ float    g_q[B*T*NH*HD];        // q projection (fp32)
__device__ float    g_k[B*T*NKV*HD];       // k projection (fp32)
__device__ float    g_v[B*T*NKV*HD];       // v mixed (fp32, packed by v_pack)
__device__ float    g_y[B*T*NH*HD];        // attention output (gate folded in)
__device__ float    g_gate[B*T*NH];        // sigmoid gate
__device__ uint32_t g_qh[B*T*NH*(HD/2)];   // q normed/roped/gained: packed bf16x2 hi
__device__ uint32_t g_qm[B*T*NH*(HD/2)];   // ... residual plane
__device__ uint32_t g_kh[B*T*NKV*(HD/2)];
__device__ uint32_t g_km[B*T*NKV*(HD/2)];
__device__ uint32_t g_vth[B*NKV*(T/2)*HD]; // v packed along t-pairs: [b][kv][t/2][d]
__device__ uint32_t g_vtm[B*NKV*(T/2)*HD];

// ---------------- bf16 helpers ----------------
__device__ __forceinline__ void mma_bf16(float* c, const uint32_t* a, const uint32_t* b) {
    asm volatile(
        "mma.sync.aligned.m16n8k16.row.col.f32.bf16.bf16.f32 "
        "{%0,%1,%2,%3}, {%4,%5,%6,%7}, {%8,%9}, {%0,%1,%2,%3};\n"
        : "+f"(c[0]), "+f"(c[1]), "+f"(c[2]), "+f"(c[3])
        : "r"(a[0]), "r"(a[1]), "r"(a[2]), "r"(a[3]), "r"(b[0]), "r"(b[1]));
}

// pack (x0,x1) -> bf16x2 hi word (low half = x0) and bf16x2 residual word
__device__ __forceinline__ void split2_pack(float x0, float x1, uint32_t& wh, uint32_t& wm) {
    asm("cvt.rn.bf16x2.f32 %0, %1, %2;" : "=r"(wh) : "f"(x1), "f"(x0));
    float h0 = __uint_as_float(wh << 16);
    float h1 = __uint_as_float(wh & 0xffff0000u);
    asm("cvt.rn.bf16x2.f32 %0, %1, %2;" : "=r"(wm) : "f"(x1 - h1), "f"(x0 - h0));
}

// ---------------- fused bf16-split GEMM (unchanged, proven) ----------------
// job=0: QKV fused. grid.x: [0,8)=Q, [8,10)=K, [10,12)=V (+v epilogue).
// job=1: O projection (A = g_y, C = out).
__global__ __launch_bounds__(256)
void gemm_bf16(const float* __restrict__ x,  const float* __restrict__ qw,
               const float* __restrict__ kw, const float* __restrict__ vw,
               const float* __restrict__ ow, const float* __restrict__ ve,
               const float* __restrict__ v0, const float* __restrict__ lam,
               float* __restrict__ out, float* __restrict__ raw_out, int job) {
    __shared__ uint32_t Ah[2][128*PSTR], Am[2][128*PSTR];
    __shared__ uint32_t Bh[2][128*PSTR], Bm[2][128*PSTR];

    const float* A; const float* W; float* C = nullptr; int N, n0; bool vjob = false;
    if (job == 0) {
        A = x;
        int bx = blockIdx.x;
        if (bx < 8)       { W = qw; C = g_q; N = NH*HD;  n0 = bx * 128; }
        else if (bx < 10) { W = kw; C = g_k; N = NKV*HD; n0 = (bx - 8) * 128; }
        else              { W = vw; C = g_v; N = NKV*HD; n0 = (bx - 10) * 128; vjob = true; }
    } else {
        A = g_y; W = ow; C = out; N = D; n0 = blockIdx.x * 128;
    }
    const int K = D;
    const int m0 = blockIdx.y * 128;

    const int tid  = threadIdx.x;
    const int lane = tid & 31;
    const int w    = tid >> 5;
    const int wm   = w & 1;
    const int wn   = w >> 1;
    const int tq   = lane >> 2;
    const int tr   = lane & 3;

    const int lrow = tid >> 1;
    const int lc8  = (tid & 1) * 8;
    const int lw   = (tid & 1) * 4;

    const float* aN = A + (size_t)(m0 + lrow) * K + lc8;
    const float* bN = W + (size_t)(n0 + lrow) * K + lc8;

    float c[16][4];
    #pragma unroll
    for (int i = 0; i < 16; i++)
        #pragma unroll
        for (int j = 0; j < 4; j++) c[i][j] = 0.f;

    {
        float4 a0 = *(const float4*)(aN);
        float4 a1 = *(const float4*)(aN + 4);
        float4 b0 = *(const float4*)(bN);
        float4 b1 = *(const float4*)(bN + 4);
        uint32_t h[4], m[4];
        split2_pack(a0.x, a0.y, h[0], m[0]); split2_pack(a0.z, a0.w, h[1], m[1]);
        split2_pack(a1.x, a1.y, h[2], m[2]); split2_pack(a1.z, a1.w, h[3], m[3]);
        *(uint4*)&Ah[0][lrow*PSTR + lw] = make_uint4(h[0], h[1], h[2], h[3]);
        *(uint4*)&Am[0][lrow*PSTR + lw] = make_uint4(m[0], m[1], m[2], m[3]);
        split2_pack(b0.x, b0.y, h[0], m[0]); split2_pack(b0.z, b0.w, h[1], m[1]);
        split2_pack(b1.x, b1.y, h[2], m[2]); split2_pack(b1.z, b1.w, h[3], m[3]);
        *(uint4*)&Bh[0][lrow*PSTR + lw] = make_uint4(h[0], h[1], h[2], h[3]);
        *(uint4*)&Bm[0][lrow*PSTR + lw] = make_uint4(m[0], m[1], m[2], m[3]);
    }
    __syncthreads();

    const int niter = K / 16;
    int cur = 0;
    for (int it = 0; it < niter; it++) {
        float4 pa0, pa1, pb0, pb1;
        const bool has_next = (it + 1 < niter);
        if (has_next) {
            int k0 = (it + 1) * 16;
            pa0 = *(const float4*)(aN + k0);
            pa1 = *(const float4*)(aN + k0 + 4);
            pb0 = *(const float4*)(bN + k0);
            pb1 = *(const float4*)(bN + k0 + 4);
        }

        const uint32_t* ah = Ah[cur]; const uint32_t* am = Am[cur];
        const uint32_t* bh = Bh[cur]; const uint32_t* bm = Bm[cur];

        uint32_t afh[4][4], afm[4][4], bfh[4][2], bfm[4][2];
        #pragma unroll
        for (int mi = 0; mi < 4; mi++) {
            int r = wm * 64 + mi * 16 + tq;
            afh[mi][0] = ah[r*PSTR + tr];     afh[mi][1] = ah[(r+8)*PSTR + tr];
            afh[mi][2] = ah[r*PSTR + tr + 4]; afh[mi][3] = ah[(r+8)*PSTR + tr + 4];
            afm[mi][0] = am[r*PSTR + tr];     afm[mi][1] = am[(r+8)*PSTR + tr];
            afm[mi][2] = am[r*PSTR + tr + 4]; afm[mi][3] = am[(r+8)*PSTR + tr + 4];
        }
        #pragma unroll
        for (int ni = 0; ni < 4; ni++) {
            int rn = wn * 32 + ni * 8 + tq;
            bfh[ni][0] = bh[rn*PSTR + tr]; bfh[ni][1] = bh[rn*PSTR + tr + 4];
            bfm[ni][0] = bm[rn*PSTR + tr]; bfm[ni][1] = bm[rn*PSTR + tr + 4];
        }
        #pragma unroll
        for (int mi = 0; mi < 4; mi++)
            #pragma unroll
            for (int ni = 0; ni < 4; ni++) {
                mma_bf16(c[mi*4+ni], afh[mi], bfh[ni]);
                mma_bf16(c[mi*4+ni], afh[mi], bfm[ni]);
                mma_bf16(c[mi*4+ni], afm[mi], bfh[ni]);
            }

        if (has_next) {
            int nxt = cur ^ 1;
            uint32_t h[4], m[4];
            split2_pack(pa0.x, pa0.y, h[0], m[0]); split2_pack(pa0.z, pa0.w, h[1], m[1]);
            split2_pack(pa1.x, pa1.y, h[2], m[2]); split2_pack(pa1.z, pa1.w, h[3], m[3]);
            *(uint4*)&Ah[nxt][lrow*PSTR + lw] = make_uint4(h[0], h[1], h[2], h[3]);
            *(uint4*)&Am[nxt][lrow*PSTR + lw] = make_uint4(m[0], m[1], m[2], m[3]);
            split2_pack(pb0.x, pb0.y, h[0], m[0]); split2_pack(pb0.z, pb0.w, h[1], m[1]);
            split2_pack(pb1.x, pb1.y, h[2], m[2]); split2_pack(pb1.z, pb1.w, h[3], m[3]);
            *(uint4*)&Bh[nxt][lrow*PSTR + lw] = make_uint4(h[0], h[1], h[2], h[3]);
            *(uint4*)&Bm[nxt][lrow*PSTR + lw] = make_uint4(m[0], m[1], m[2], m[3]);
            __syncthreads();
            cur = nxt;
        }
    }

    if (!vjob) {
        #pragma unroll
        for (int mi = 0; mi < 4; mi++)
            #pragma unroll
            for (int ni = 0; ni < 4; ni++) {
                int row = m0 + wm*64 + mi*16 + tq;
                int col = n0 + wn*32 + ni*8 + 2*tr;
                float* cp = c[mi*4+ni];
                *(float2*)(C + (size_t)row * N + col)       = make_float2(cp[0], cp[1]);
                *(float2*)(C + (size_t)(row + 8) * N + col) = make_float2(cp[2], cp[3]);
            }
    } else {
        const float l0 = lam[0], l1 = lam[1];
        #pragma unroll
        for (int mi = 0; mi < 4; mi++)
            #pragma unroll
            for (int ni = 0; ni < 4; ni++) {
                int row = m0 + wm*64 + mi*16 + tq;
                int col = n0 + wn*32 + ni*8 + 2*tr;
                float* cp = c[mi*4+ni];
                #pragma unroll
                for (int half = 0; half < 2; half++) {
                    size_t gi = (size_t)(row + half*8) * N + col;
                    float2 vee = *(const float2*)(ve + gi);
                    float2 v00 = *(const float2*)(v0 + gi);
                    float r0 = cp[half*2]   + vee.x;
                    float r1 = cp[half*2+1] + vee.y;
                    *(float2*)(raw_out + gi) = make_float2(r0, r1);
                    *(float2*)(C + gi) = make_float2(l0*v00.x + l1*r0, l0*v00.y + l1*r1);
                }
            }
    }
}

// ---------------- RMSNorm + RoPE (+gain), emit packed bf16x2 hi/mid planes ----------------
// buf 0: Q (g_q -> g_qh/g_qm), buf 1: K (g_k -> g_kh/g_km). Resolved device-side.
__global__ void rmsnorm_rope_pack(int buf, const float* __restrict__ gain, int H, double nb) {
    const float* src; uint32_t* dh; uint32_t* dm;
    if (buf == 0) { src = g_q; dh = g_qh; dm = g_qm; }
    else          { src = g_k; dh = g_kh; dm = g_km; }

    int row  = blockIdx.x * 8 + (threadIdx.x >> 5);
    int lane = threadIdx.x & 31;
    int t = (row / H) % T;
    int h = row % H;
    const float* p = src + (size_t)row * HD;

    float a  = p[lane];
    float b2 = p[lane + 32];
    float ss = a*a + b2*b2;
    #pragma unroll
    for (int o = 16; o; o >>= 1) ss += __shfl_xor_sync(0xffffffffu, ss, o);
    float r = rsqrtf(ss * (1.0f/HD) + EPSF);
    a *= r; b2 *= r;

    float inv = (float)pow(nb, -(double)(2*lane) / (double)HD);
    float fr  = (float)t * inv;
    float cc = (float)cos((double)fr);
    float sn = (float)sin((double)fr);

    float o1 =  a*cc + b2*sn;          // d = lane
    float o2 = -a*sn + b2*cc;          // d = lane + 32
    if (gain) { float gg = gain[h]; o1 *= gg; o2 *= gg; }

    // pack adjacent-d pairs: even lane packs (o1_self, o1_next); odd lane packs (o2_prev, o2_self)
    float p1 = __shfl_xor_sync(0xffffffffu, o1, 1);
    float p2 = __shfl_xor_sync(0xffffffffu, o2, 1);
    uint32_t wh, wmv; int widx;
    if (lane & 1) { split2_pack(p2, o2, wh, wmv); widx = 16 + (lane >> 1); }
    else          { split2_pack(o1, p1, wh, wmv); widx = lane >> 1; }
    dh[(size_t)row * 32 + widx] = wh;
    dm[(size_t)row * 32 + widx] = wmv;
}

// ---------------- V pack: g_v [b][t][kv][d] -> t-pair packed planes [b][kv][t/2][d] ----------------
__global__ void v_pack() {
    int idx = blockIdx.x * 256 + threadIdx.x;    // 524288 words
    int d  = idx & 63;
    int tp = (idx >> 6) & (T/2 - 1);
    int kv = (idx >> 16) & 3;
    int b  = idx >> 18;
    float a  = g_v[((size_t)(b*T + 2*tp)     * NKV + kv) * HD + d];
    float b2 = g_v[((size_t)(b*T + 2*tp + 1) * NKV + kv) * HD + d];
    uint32_t wh, wmv;
    split2_pack(a, b2, wh, wmv);
    g_vth[idx] = wh;
    g_vtm[idx] = wmv;
}

// ---------------- gate: sigmoid(x @ gate_w^T + gate_b), one block per (b,t) ----------------
__global__ void gate_kernel(const float* __restrict__ x, const float* __restrict__ gw,
                            const float* __restrict__ gb) {
    __shared__ float xs[D];
    int bt = blockIdx.x;
    for (int i = threadIdx.x; i < D; i += 512) xs[i] = x[(size_t)bt * D + i];
    __syncthreads();
    int h = threadIdx.x >> 5, lane = threadIdx.x & 31;
    const float* w = gw + (size_t)h * D;
    float s = 0.f;
    for (int i = lane; i < D; i += 32) s += xs[i] * w[i];
    #pragma unroll
    for (int o = 16; o; o >>= 1) s += __shfl_xor_sync(0xffffffffu, s, o);
    if (lane == 0) g_gate[bt * NH + h] = 1.0f / (1.0f + __expf(-(s + gb[h])));
}

// ---------------- bf16 flash attention, pre-split global planes ----------------
// 4 warps, 64 q rows per CTA, 64-kv tiles. Tile loads = pure uint4 copies;
// every K/V fragment word = ONE conflict-free LDS. Only P splits remain in-loop.
__global__ __launch_bounds__(128)
void attn_bf16() {
    __shared__ uint32_t Kh[64*KSTR], Km[64*KSTR];   // [key n][k/2 word]
    __shared__ uint32_t Vh[32*VSTR], Vm[32*VSTR];   // [t-pair][d]

    const int qt = (int)gridDim.x - 1 - (int)blockIdx.x;   // heavy tiles first
    const int h = blockIdx.y, b = blockIdx.z;
    const int kv = h / GQ;
    const int tid = threadIdx.x;
    const int w = tid >> 5, lane = tid & 31;
    const int tq = lane >> 2, tr = lane & 3;
    const int r0 = w * 16 + tq;      // warp-local q row (and +8)

    // ---- persistent Q fragments straight from packed planes ----
    uint32_t qh[4][4], qm[4][4];
    {
        const size_t qA = ((size_t)(b*T + qt*64 + r0) * NH + h) * 32;
        const size_t qB = qA + (size_t)8 * NH * 32;
        #pragma unroll
        for (int kb = 0; kb < 4; kb++) {
            qh[kb][0] = g_qh[qA + kb*8 + tr];     qh[kb][1] = g_qh[qB + kb*8 + tr];
            qh[kb][2] = g_qh[qA + kb*8 + tr + 4]; qh[kb][3] = g_qh[qB + kb*8 + tr + 4];
            qm[kb][0] = g_qm[qA + kb*8 + tr];     qm[kb][1] = g_qm[qB + kb*8 + tr];
            qm[kb][2] = g_qm[qA + kb*8 + tr + 4]; qm[kb][3] = g_qm[qB + kb*8 + tr + 4];
        }
    }

    float o[8][4];
    #pragma unroll
    for (int ni = 0; ni < 8; ni++)
        #pragma unroll
        for (int j = 0; j < 4; j++) o[ni][j] = 0.f;
    float m0r = -1e30f, m1r = -1e30f, l0r = 0.f, l1r = 0.f;

    const size_t kbase = ((size_t)(b*T) * NKV + kv) * 32;          // + t*NKV*32
    const size_t vbase = ((size_t)(b*NKV + kv)) * (T/2) * 64;      // + tp*64

    for (int kt = 0; kt <= qt; kt++) {
        const int t0 = kt * 64;
        __syncthreads();
        // K planes: 64 rows x 8 uint4-chunks each
        #pragma unroll
        for (int ci = 0; ci < 4; ci++) {
            int i = tid + ci * 128;
            int r = i >> 3, j = (i & 7) * 4;
            size_t src = kbase + (size_t)(t0 + r) * (NKV*32) + j;
            *(uint4*)&Kh[r*KSTR + j] = *(const uint4*)&g_kh[src];
            *(uint4*)&Km[r*KSTR + j] = *(const uint4*)&g_km[src];
        }
        // V planes: 32 t-pairs x 16 uint4-chunks each
        #pragma unroll
        for (int ci = 0; ci < 4; ci++) {
            int i = tid + ci * 128;
            int tp = i >> 4, j = (i & 15) * 4;
            size_t src = vbase + (size_t)(t0/2 + tp) * 64 + j;
            *(uint4*)&Vh[tp*VSTR + j] = *(const uint4*)&g_vth[src];
            *(uint4*)&Vm[tp*VSTR + j] = *(const uint4*)&g_vtm[src];
        }
        __syncthreads();

        // ---- S = Q @ K^T ----
        float s[8][4];
        #pragma unroll
        for (int ni = 0; ni < 8; ni++) {
            s[ni][0] = s[ni][1] = s[ni][2] = s[ni][3] = 0.f;
            const int kn = (ni*8 + tq) * KSTR;
            #pragma unroll
            for (int kb = 0; kb < 4; kb++) {
                uint32_t bh[2], bm[2];
                bh[0] = Kh[kn + kb*8 + tr]; bh[1] = Kh[kn + kb*8 + tr + 4];
                bm[0] = Km[kn + kb*8 + tr]; bm[1] = Km[kn + kb*8 + tr + 4];
                mma_bf16(s[ni], qh[kb], bh);
                mma_bf16(s[ni], qh[kb], bm);
                mma_bf16(s[ni], qm[kb], bh);
            }
        }

        // ---- causal mask (diagonal tile only) ----
        const int rowa = qt*64 + r0, rowb = rowa + 8;
        if (kt == qt) {
            #pragma unroll
            for (int ni = 0; ni < 8; ni++) {
                int col = t0 + ni*8 + 2*tr;
                if (col     > rowa) s[ni][0] = -1e30f;
                if (col + 1 > rowa) s[ni][1] = -1e30f;
                if (col     > rowb) s[ni][2] = -1e30f;
                if (col + 1 > rowb) s[ni][3] = -1e30f;
            }
        }

        // ---- online softmax (logits = s * 0.125) ----
        const float SC = 0.125f;
        float mx0 = -1e30f, mx1 = -1e30f;
        #pragma unroll
        for (int ni = 0; ni < 8; ni++) {
            mx0 = fmaxf(mx0, fmaxf(s[ni][0], s[ni][1]));
            mx1 = fmaxf(mx1, fmaxf(s[ni][2], s[ni][3]));
        }
        mx0 = fmaxf(mx0, __shfl_xor_sync(0xffffffffu, mx0, 1));
        mx0 = fmaxf(mx0, __shfl_xor_sync(0xffffffffu, mx0, 2));
        mx1 = fmaxf(mx1, __shfl_xor_sync(0xffffffffu, mx1, 1));
        mx1 = fmaxf(mx1, __shfl_xor_sync(0xffffffffu, mx1, 2));
        float mn0 = fmaxf(m0r, mx0 * SC);
        float mn1 = fmaxf(m1r, mx1 * SC);
        float al0 = exp2f((m0r - mn0) * LOG2E);
        float al1 = exp2f((m1r - mn1) * LOG2E);
        m0r = mn0; m1r = mn1;

        float sum0 = 0.f, sum1 = 0.f;
        #pragma unroll
        for (int ni = 0; ni < 8; ni++) {
            float p0 = exp2f((s[ni][0] * SC - mn0) * LOG2E);
            float p1 = exp2f((s[ni][1] * SC - mn0) * LOG2E);
            float p2 = exp2f((s[ni][2] * SC - mn1) * LOG2E);
            float p3 = exp2f((s[ni][3] * SC - mn1) * LOG2E);
            s[ni][0] = p0; s[ni][1] = p1; s[ni][2] = p2; s[ni][3] = p3;
            sum0 += p0 + p1; sum1 += p2 + p3;
            o[ni][0] *= al0; o[ni][1] *= al0; o[ni][2] *= al1; o[ni][3] *= al1;
        }
        sum0 += __shfl_xor_sync(0xffffffffu, sum0, 1);
        sum0 += __shfl_xor_sync(0xffffffffu, sum0, 2);
        sum1 += __shfl_xor_sync(0xffffffffu, sum1, 1);
        sum1 += __shfl_xor_sync(0xffffffffu, sum1, 2);
        l0r = l0r * al0 + sum0;
        l1r = l1r * al1 + sum1;

        // ---- O += P @ V; A-fragments from S C-fragments, V words single LDS ----
        #pragma unroll
        for (int c0 = 0; c0 < 4; c0++) {
            uint32_t ph[4], pm[4];
            split2_pack(s[2*c0][0],   s[2*c0][1],   ph[0], pm[0]);
            split2_pack(s[2*c0][2],   s[2*c0][3],   ph[1], pm[1]);
            split2_pack(s[2*c0+1][0], s[2*c0+1][1], ph[2], pm[2]);
            split2_pack(s[2*c0+1][2], s[2*c0+1][3], ph[3], pm[3]);
            const int ra = (c0*8 + tr) * VSTR;
            const int rb = ra + 4*VSTR;
            #pragma unroll
            for (int ni = 0; ni < 8; ni++) {
                const int dd = ni*8 + tq;
                uint32_t vh[2], vm[2];
                vh[0] = Vh[ra + dd]; vh[1] = Vh[rb + dd];
                vm[0] = Vm[ra + dd]; vm[1] = Vm[rb + dd];
                mma_bf16(o[ni], ph, vh);
                mma_bf16(o[ni], ph, vm);
                mma_bf16(o[ni], pm, vh);
            }
        }
    }

    // ---- epilogue: y = o / l * gate ----
    const int rowa = qt*64 + r0, rowb = rowa + 8;
    float g0 = g_gate[(b*T + rowa) * NH + h] / l0r;
    float g1 = g_gate[(b*T + rowb) * NH + h] / l1r;
    #pragma unroll
    for (int ni = 0; ni < 8; ni++) {
        int col = ni*8 + 2*tr;
        size_t ba = ((size_t)(b*T + rowa) * NH + h) * HD + col;
        size_t bb = ((size_t)(b*T + rowb) * NH + h) * HD + col;
        *(float2*)(g_y + ba) = make_float2(o[ni][0] * g0, o[ni][1] * g0);
        *(float2*)(g_y + bb) = make_float2(o[ni][2] * g1, o[ni][3] * g1);
    }
}

// ---------------- launch ----------------
extern "C" void kernel_launch(void* const* d_in, const int* in_sizes, int n_in,
                              void* d_out, int out_size) {
    (void)in_sizes; (void)n_in; (void)out_size;
    const float* x  = (const float*)d_in[0];
    const float* qw = (const float*)d_in[1];
    const float* kw = (const float*)d_in[2];
    const float* vw = (const float*)d_in[3];
    const float* ow = (const float*)d_in[4];
    const float* ve = (const float*)d_in[5];
    const float* v0 = (const float*)d_in[6];
    const float* qg = (const float*)d_in[7];
    const float* vl = (const float*)d_in[8];
    const float* gw = (const float*)d_in[9];
    const float* gb = (const float*)d_in[10];

    float* out     = (float*)d_out;
    float* raw_out = out + (size_t)B * T * D;     // second output: raw_v

    // NTK-scaled base: T=2048 > TSL=1024
    const double nb = 10000.0 * pow((double)T / 1024.0, 64.0 / 62.0);

    // fused QKV projections (+ V epilogue folded into V tiles)
    gemm_bf16<<<dim3(12, (B*T)/128), 256>>>(x, qw, kw, vw, nullptr, ve, v0, vl,
                                            nullptr, raw_out, 0);

    // rmsnorm + rope (+ q gain) -> packed bf16x2 planes
    rmsnorm_rope_pack<<<(B*T*NH)/8,  256>>>(0, qg,      NH,  nb);
    rmsnorm_rope_pack<<<(B*T*NKV)/8, 256>>>(1, nullptr, NKV, nb);

    // pack mixed V into t-pair planes
    v_pack<<<(B*NKV*(T/2)*HD)/256, 256>>>();

    // gate
    gate_kernel<<<B*T, 512>>>(x, gw, gb);

    // bf16 tensor-core attention (gate folded into epilogue)
    attn_bf16<<<dim3(T/64, NH, B), 128>>>();

    // output projection
    gemm_bf16<<<dim3(D/128, (B*T)/128), 256>>>(nullptr, nullptr, nullptr, nullptr, ow,
                                               nullptr, nullptr, nullptr, out, nullptr, 1);
}

// round 12
// speedup vs baseline: 1.6876x; 1.0305x over previous
#include <cuda_runtime.h>
#include <cuda_fp16.h>
#include <math.h>
#include <stdint.h>

#define B   2
#define T   2048
#define D   1024
#define NH  16
#define NKV 4
#define HD  64
#define GQ  4            // NH / NKV
#define EPSF 1.1920929e-07f
#define LOG2E 1.4426950408889634f
#define PSTR 12          // GEMM smem word stride (8 data + 4 pad) -> conflict-free frags
#define KSTR 36          // attn K plane stride: 36 mod 32 = 4 -> banks 4tq+tr (perm)
#define VSTR 72          // attn V plane stride: 72 mod 32 = 8 -> banks 8tr+tq (perm)

// ---------------- scratch (no allocations allowed) ----------------
__device__ float    g_q[B*T*NH*HD];        // q projection (fp32)
__device__ float    g_k[B*T*NKV*HD];       // k projection (fp32)
__device__ float    g_v[B*T*NKV*HD];       // v mixed (fp32)
__device__ float    g_y[B*T*NH*HD];        // attention output (gate folded in)
__device__ float    g_gate[B*T*NH];        // sigmoid gate
__device__ uint32_t g_qh[B*T*NH*(HD/2)];   // q normed/roped/gained: packed fp16x2 (hi only)
__device__ uint32_t g_kh[B*T*NKV*(HD/2)];  // k: fp16x2 hi plane
__device__ uint32_t g_km[B*T*NKV*(HD/2)];  // k: fp16x2 residual plane
__device__ uint32_t g_vth[B*NKV*(T/2)*HD]; // v packed along t-pairs: [b][kv][t/2][d] hi
__device__ uint32_t g_vtm[B*NKV*(T/2)*HD]; // ... residual

__device__ __forceinline__ float* scratch_buf(int id) {
    switch (id) {
        case 0: return g_q;
        case 1: return g_k;
        default: return g_v;
    }
}

// ---------------- mma helpers ----------------
__device__ __forceinline__ void mma_bf16(float* c, const uint32_t* a, const uint32_t* b) {
    asm volatile(
        "mma.sync.aligned.m16n8k16.row.col.f32.bf16.bf16.f32 "
        "{%0,%1,%2,%3}, {%4,%5,%6,%7}, {%8,%9}, {%0,%1,%2,%3};\n"
        : "+f"(c[0]), "+f"(c[1]), "+f"(c[2]), "+f"(c[3])
        : "r"(a[0]), "r"(a[1]), "r"(a[2]), "r"(a[3]), "r"(b[0]), "r"(b[1]));
}
__device__ __forceinline__ void mma_f16(float* c, const uint32_t* a, const uint32_t* b) {
    asm volatile(
        "mma.sync.aligned.m16n8k16.row.col.f32.f16.f16.f32 "
        "{%0,%1,%2,%3}, {%4,%5,%6,%7}, {%8,%9}, {%0,%1,%2,%3};\n"
        : "+f"(c[0]), "+f"(c[1]), "+f"(c[2]), "+f"(c[3])
        : "r"(a[0]), "r"(a[1]), "r"(a[2]), "r"(a[3]), "r"(b[0]), "r"(b[1]));
}

// bf16 split: (x0,x1) -> hi word + residual word (GEMM path, proven)
__device__ __forceinline__ void split2_pack(float x0, float x1, uint32_t& wh, uint32_t& wm) {
    asm("cvt.rn.bf16x2.f32 %0, %1, %2;" : "=r"(wh) : "f"(x1), "f"(x0));
    float h0 = __uint_as_float(wh << 16);
    float h1 = __uint_as_float(wh & 0xffff0000u);
    asm("cvt.rn.bf16x2.f32 %0, %1, %2;" : "=r"(wm) : "f"(x1 - h1), "f"(x0 - h0));
}

// fp16 split: (x0,x1) -> hi word + residual word (attention path)
__device__ __forceinline__ void split2_pack_f16(float x0, float x1, uint32_t& wh, uint32_t& wm) {
    __half2 h = __floats2half2_rn(x0, x1);
    wh = *(uint32_t*)&h;
    float2 hf = __half22float2(h);
    __half2 m = __floats2half2_rn(x0 - hf.x, x1 - hf.y);
    wm = *(uint32_t*)&m;
}
__device__ __forceinline__ uint32_t pack_f16(float x0, float x1) {
    __half2 h = __floats2half2_rn(x0, x1);
    return *(uint32_t*)&h;
}

// ---------------- fused bf16-split GEMM (R9/R10 proven, unchanged) ----------------
// job=0: QKV fused. grid.x: [0,8)=Q, [8,10)=K, [10,12)=V (+v epilogue).
// job=1: O projection (A = g_y, C = out).
__global__ __launch_bounds__(256)
void gemm_bf16(const float* __restrict__ x,  const float* __restrict__ qw,
               const float* __restrict__ kw, const float* __restrict__ vw,
               const float* __restrict__ ow, const float* __restrict__ ve,
               const float* __restrict__ v0, const float* __restrict__ lam,
               float* __restrict__ out, float* __restrict__ raw_out, int job) {
    __shared__ uint32_t Ah[2][128*PSTR], Am[2][128*PSTR];
    __shared__ uint32_t Bh[2][128*PSTR], Bm[2][128*PSTR];

    const float* A; const float* W; float* C = nullptr; int N, n0; bool vjob = false;
    if (job == 0) {
        A = x;
        int bx = blockIdx.x;
        if (bx < 8)       { W = qw; C = g_q; N = NH*HD;  n0 = bx * 128; }
        else if (bx < 10) { W = kw; C = g_k; N = NKV*HD; n0 = (bx - 8) * 128; }
        else              { W = vw; C = g_v; N = NKV*HD; n0 = (bx - 10) * 128; vjob = true; }
    } else {
        A = g_y; W = ow; C = out; N = D; n0 = blockIdx.x * 128;
    }
    const int K = D;
    const int m0 = blockIdx.y * 128;

    const int tid  = threadIdx.x;
    const int lane = tid & 31;
    const int w    = tid >> 5;
    const int wm   = w & 1;
    const int wn   = w >> 1;
    const int tq   = lane >> 2;
    const int tr   = lane & 3;

    const int lrow = tid >> 1;
    const int lc8  = (tid & 1) * 8;
    const int lw   = (tid & 1) * 4;

    const float* aN = A + (size_t)(m0 + lrow) * K + lc8;
    const float* bN = W + (size_t)(n0 + lrow) * K + lc8;

    float c[16][4];
    #pragma unroll
    for (int i = 0; i < 16; i++)
        #pragma unroll
        for (int j = 0; j < 4; j++) c[i][j] = 0.f;

    {
        float4 a0 = *(const float4*)(aN);
        float4 a1 = *(const float4*)(aN + 4);
        float4 b0 = *(const float4*)(bN);
        float4 b1 = *(const float4*)(bN + 4);
        uint32_t h[4], m[4];
        split2_pack(a0.x, a0.y, h[0], m[0]); split2_pack(a0.z, a0.w, h[1], m[1]);
        split2_pack(a1.x, a1.y, h[2], m[2]); split2_pack(a1.z, a1.w, h[3], m[3]);
        *(uint4*)&Ah[0][lrow*PSTR + lw] = make_uint4(h[0], h[1], h[2], h[3]);
        *(uint4*)&Am[0][lrow*PSTR + lw] = make_uint4(m[0], m[1], m[2], m[3]);
        split2_pack(b0.x, b0.y, h[0], m[0]); split2_pack(b0.z, b0.w, h[1], m[1]);
        split2_pack(b1.x, b1.y, h[2], m[2]); split2_pack(b1.z, b1.w, h[3], m[3]);
        *(uint4*)&Bh[0][lrow*PSTR + lw] = make_uint4(h[0], h[1], h[2], h[3]);
        *(uint4*)&Bm[0][lrow*PSTR + lw] = make_uint4(m[0], m[1], m[2], m[3]);
    }
    __syncthreads();

    const int niter = K / 16;
    int cur = 0;
    for (int it = 0; it < niter; it++) {
        float4 pa0, pa1, pb0, pb1;
        const bool has_next = (it + 1 < niter);
        if (has_next) {
            int k0 = (it + 1) * 16;
            pa0 = *(const float4*)(aN + k0);
            pa1 = *(const float4*)(aN + k0 + 4);
            pb0 = *(const float4*)(bN + k0);
            pb1 = *(const float4*)(bN + k0 + 4);
        }

        const uint32_t* ah = Ah[cur]; const uint32_t* am = Am[cur];
        const uint32_t* bh = Bh[cur]; const uint32_t* bm = Bm[cur];

        uint32_t afh[4][4], afm[4][4], bfh[4][2], bfm[4][2];
        #pragma unroll
        for (int mi = 0; mi < 4; mi++) {
            int r = wm * 64 + mi * 16 + tq;
            afh[mi][0] = ah[r*PSTR + tr];     afh[mi][1] = ah[(r+8)*PSTR + tr];
            afh[mi][2] = ah[r*PSTR + tr + 4]; afh[mi][3] = ah[(r+8)*PSTR + tr + 4];
            afm[mi][0] = am[r*PSTR + tr];     afm[mi][1] = am[(r+8)*PSTR + tr];
            afm[mi][2] = am[r*PSTR + tr + 4]; afm[mi][3] = am[(r+8)*PSTR + tr + 4];
        }
        #pragma unroll
        for (int ni = 0; ni < 4; ni++) {
            int rn = wn * 32 + ni * 8 + tq;
            bfh[ni][0] = bh[rn*PSTR + tr]; bfh[ni][1] = bh[rn*PSTR + tr + 4];
            bfm[ni][0] = bm[rn*PSTR + tr]; bfm[ni][1] = bm[rn*PSTR + tr + 4];
        }
        #pragma unroll
        for (int mi = 0; mi < 4; mi++)
            #pragma unroll
            for (int ni = 0; ni < 4; ni++) {
                mma_bf16(c[mi*4+ni], afh[mi], bfh[ni]);
                mma_bf16(c[mi*4+ni], afh[mi], bfm[ni]);
                mma_bf16(c[mi*4+ni], afm[mi], bfh[ni]);
            }

        if (has_next) {
            int nxt = cur ^ 1;
            uint32_t h[4], m[4];
            split2_pack(pa0.x, pa0.y, h[0], m[0]); split2_pack(pa0.z, pa0.w, h[1], m[1]);
            split2_pack(pa1.x, pa1.y, h[2], m[2]); split2_pack(pa1.z, pa1.w, h[3], m[3]);
            *(uint4*)&Ah[nxt][lrow*PSTR + lw] = make_uint4(h[0], h[1], h[2], h[3]);
            *(uint4*)&Am[nxt][lrow*PSTR + lw] = make_uint4(m[0], m[1], m[2], m[3]);
            split2_pack(pb0.x, pb0.y, h[0], m[0]); split2_pack(pb0.z, pb0.w, h[1], m[1]);
            split2_pack(pb1.x, pb1.y, h[2], m[2]); split2_pack(pb1.z, pb1.w, h[3], m[3]);
            *(uint4*)&Bh[nxt][lrow*PSTR + lw] = make_uint4(h[0], h[1], h[2], h[3]);
            *(uint4*)&Bm[nxt][lrow*PSTR + lw] = make_uint4(m[0], m[1], m[2], m[3]);
            __syncthreads();
            cur = nxt;
        }
    }

    if (!vjob) {
        #pragma unroll
        for (int mi = 0; mi < 4; mi++)
            #pragma unroll
            for (int ni = 0; ni < 4; ni++) {
                int row = m0 + wm*64 + mi*16 + tq;
                int col = n0 + wn*32 + ni*8 + 2*tr;
                float* cp = c[mi*4+ni];
                *(float2*)(C + (size_t)row * N + col)       = make_float2(cp[0], cp[1]);
                *(float2*)(C + (size_t)(row + 8) * N + col) = make_float2(cp[2], cp[3]);
            }
    } else {
        const float l0 = lam[0], l1 = lam[1];
        #pragma unroll
        for (int mi = 0; mi < 4; mi++)
            #pragma unroll
            for (int ni = 0; ni < 4; ni++) {
                int row = m0 + wm*64 + mi*16 + tq;
                int col = n0 + wn*32 + ni*8 + 2*tr;
                float* cp = c[mi*4+ni];
                #pragma unroll
                for (int half = 0; half < 2; half++) {
                    size_t gi = (size_t)(row + half*8) * N + col;
                    float2 vee = *(const float2*)(ve + gi);
                    float2 v00 = *(const float2*)(v0 + gi);
                    float r0 = cp[half*2]   + vee.x;
                    float r1 = cp[half*2+1] + vee.y;
                    *(float2*)(raw_out + gi) = make_float2(r0, r1);
                    *(float2*)(C + gi) = make_float2(l0*v00.x + l1*r0, l0*v00.y + l1*r1);
                }
            }
    }
}

// ---------------- RMSNorm + RoPE (+gain), emit packed fp16x2 planes ----------------
// buf 0: Q -> g_qh only (hi, fp16-rounded). buf 1: K -> g_kh + g_km (hi + residual).
__global__ void rmsnorm_rope_pack(int buf, const float* __restrict__ gain, int H, double nb) {
    const float* src = (buf == 0) ? g_q : g_k;

    int row  = blockIdx.x * 8 + (threadIdx.x >> 5);
    int lane = threadIdx.x & 31;
    int t = (row / H) % T;
    int h = row % H;
    const float* p = src + (size_t)row * HD;

    float a  = p[lane];
    float b2 = p[lane + 32];
    float ss = a*a + b2*b2;
    #pragma unroll
    for (int o = 16; o; o >>= 1) ss += __shfl_xor_sync(0xffffffffu, ss, o);
    float r = rsqrtf(ss * (1.0f/HD) + EPSF);
    a *= r; b2 *= r;

    float inv = (float)pow(nb, -(double)(2*lane) / (double)HD);
    float fr  = (float)t * inv;
    float cc = (float)cos((double)fr);
    float sn = (float)sin((double)fr);

    float o1 =  a*cc + b2*sn;          // d = lane
    float o2 = -a*sn + b2*cc;          // d = lane + 32
    if (gain) { float gg = gain[h]; o1 *= gg; o2 *= gg; }

    float p1 = __shfl_xor_sync(0xffffffffu, o1, 1);
    float p2 = __shfl_xor_sync(0xffffffffu, o2, 1);
    uint32_t wh, wmv; int widx;
    if (lane & 1) { split2_pack_f16(p2, o2, wh, wmv); widx = 16 + (lane >> 1); }
    else          { split2_pack_f16(o1, p1, wh, wmv); widx = lane >> 1; }
    if (buf == 0) {
        g_qh[(size_t)row * 32 + widx] = wh;
    } else {
        g_kh[(size_t)row * 32 + widx] = wh;
        g_km[(size_t)row * 32 + widx] = wmv;
    }
}

// ---------------- V pack: g_v [b][t][kv][d] -> t-pair packed fp16 planes ----------------
__global__ void v_pack() {
    int idx = blockIdx.x * 256 + threadIdx.x;
    int d  = idx & 63;
    int tp = (idx >> 6) & (T/2 - 1);
    int kv = (idx >> 16) & 3;
    int b  = idx >> 18;
    float a  = g_v[((size_t)(b*T + 2*tp)     * NKV + kv) * HD + d];
    float b2 = g_v[((size_t)(b*T + 2*tp + 1) * NKV + kv) * HD + d];
    uint32_t wh, wmv;
    split2_pack_f16(a, b2, wh, wmv);
    g_vth[idx] = wh;
    g_vtm[idx] = wmv;
}

// ---------------- gate: sigmoid(x @ gate_w^T + gate_b), one block per (b,t) ----------------
__global__ void gate_kernel(const float* __restrict__ x, const float* __restrict__ gw,
                            const float* __restrict__ gb) {
    __shared__ float xs[D];
    int bt = blockIdx.x;
    for (int i = threadIdx.x; i < D; i += 512) xs[i] = x[(size_t)bt * D + i];
    __syncthreads();
    int h = threadIdx.x >> 5, lane = threadIdx.x & 31;
    const float* w = gw + (size_t)h * D;
    float s = 0.f;
    for (int i = lane; i < D; i += 32) s += xs[i] * w[i];
    #pragma unroll
    for (int o = 16; o; o >>= 1) s += __shfl_xor_sync(0xffffffffu, s, o);
    if (lane == 0) g_gate[bt * NH + h] = 1.0f / (1.0f + __expf(-(s + gb[h])));
}

// ---------------- fp16 flash attention, 2-pass QK (fp16 Q) + 2-pass PV (fp16 P) ----------------
__global__ __launch_bounds__(128)
void attn_f16() {
    __shared__ uint32_t Kh[64*KSTR], Km[64*KSTR];   // [key n][k/2 word]
    __shared__ uint32_t Vh[32*VSTR], Vm[32*VSTR];   // [t-pair][d]

    const int qt = (int)gridDim.x - 1 - (int)blockIdx.x;   // heavy tiles first
    const int h = blockIdx.y, b = blockIdx.z;
    const int kv = h / GQ;
    const int tid = threadIdx.x;
    const int w = tid >> 5, lane = tid & 31;
    const int tq = lane >> 2, tr = lane & 3;
    const int r0 = w * 16 + tq;

    // persistent Q fragments (fp16 hi only) from packed plane
    uint32_t qh[4][4];
    {
        const size_t qA = ((size_t)(b*T + qt*64 + r0) * NH + h) * 32;
        const size_t qB = qA + (size_t)8 * NH * 32;
        #pragma unroll
        for (int kb = 0; kb < 4; kb++) {
            qh[kb][0] = g_qh[qA + kb*8 + tr];     qh[kb][1] = g_qh[qB + kb*8 + tr];
            qh[kb][2] = g_qh[qA + kb*8 + tr + 4]; qh[kb][3] = g_qh[qB + kb*8 + tr + 4];
        }
    }

    float o[8][4];
    #pragma unroll
    for (int ni = 0; ni < 8; ni++)
        #pragma unroll
        for (int j = 0; j < 4; j++) o[ni][j] = 0.f;
    float m0r = -1e30f, m1r = -1e30f, l0r = 0.f, l1r = 0.f;

    const size_t kbase = ((size_t)(b*T) * NKV + kv) * 32;
    const size_t vbase = ((size_t)(b*NKV + kv)) * (T/2) * 64;

    for (int kt = 0; kt <= qt; kt++) {
        const int t0 = kt * 64;
        __syncthreads();
        #pragma unroll
        for (int ci = 0; ci < 4; ci++) {
            int i = tid + ci * 128;
            int r = i >> 3, j = (i & 7) * 4;
            size_t src = kbase + (size_t)(t0 + r) * (NKV*32) + j;
            *(uint4*)&Kh[r*KSTR + j] = *(const uint4*)&g_kh[src];
            *(uint4*)&Km[r*KSTR + j] = *(const uint4*)&g_km[src];
        }
        #pragma unroll
        for (int ci = 0; ci < 4; ci++) {
            int i = tid + ci * 128;
            int tp = i >> 4, j = (i & 15) * 4;
            size_t src = vbase + (size_t)(t0/2 + tp) * 64 + j;
            *(uint4*)&Vh[tp*VSTR + j] = *(const uint4*)&g_vth[src];
            *(uint4*)&Vm[tp*VSTR + j] = *(const uint4*)&g_vtm[src];
        }
        __syncthreads();

        // ---- S = Q @ K^T: q_f16 x (k_hi + k_mid)  [2 MMAs per step] ----
        float s[8][4];
        #pragma unroll
        for (int ni = 0; ni < 8; ni++) {
            s[ni][0] = s[ni][1] = s[ni][2] = s[ni][3] = 0.f;
            const int kn = (ni*8 + tq) * KSTR;
            #pragma unroll
            for (int kb = 0; kb < 4; kb++) {
                uint32_t bh[2], bm[2];
                bh[0] = Kh[kn + kb*8 + tr]; bh[1] = Kh[kn + kb*8 + tr + 4];
                bm[0] = Km[kn + kb*8 + tr]; bm[1] = Km[kn + kb*8 + tr + 4];
                mma_f16(s[ni], qh[kb], bh);
                mma_f16(s[ni], qh[kb], bm);
            }
        }

        // ---- causal mask (diagonal tile only) ----
        const int rowa = qt*64 + r0, rowb = rowa + 8;
        if (kt == qt) {
            #pragma unroll
            for (int ni = 0; ni < 8; ni++) {
                int col = t0 + ni*8 + 2*tr;
                if (col     > rowa) s[ni][0] = -1e30f;
                if (col + 1 > rowa) s[ni][1] = -1e30f;
                if (col     > rowb) s[ni][2] = -1e30f;
                if (col + 1 > rowb) s[ni][3] = -1e30f;
            }
        }

        // ---- online softmax (logits = s * 0.125) ----
        const float SC = 0.125f;
        float mx0 = -1e30f, mx1 = -1e30f;
        #pragma unroll
        for (int ni = 0; ni < 8; ni++) {
            mx0 = fmaxf(mx0, fmaxf(s[ni][0], s[ni][1]));
            mx1 = fmaxf(mx1, fmaxf(s[ni][2], s[ni][3]));
        }
        mx0 = fmaxf(mx0, __shfl_xor_sync(0xffffffffu, mx0, 1));
        mx0 = fmaxf(mx0, __shfl_xor_sync(0xffffffffu, mx0, 2));
        mx1 = fmaxf(mx1, __shfl_xor_sync(0xffffffffu, mx1, 1));
        mx1 = fmaxf(mx1, __shfl_xor_sync(0xffffffffu, mx1, 2));
        float mn0 = fmaxf(m0r, mx0 * SC);
        float mn1 = fmaxf(m1r, mx1 * SC);
        float al0 = exp2f((m0r - mn0) * LOG2E);
        float al1 = exp2f((m1r - mn1) * LOG2E);
        m0r = mn0; m1r = mn1;

        float sum0 = 0.f, sum1 = 0.f;
        #pragma unroll
        for (int ni = 0; ni < 8; ni++) {
            float p0 = exp2f((s[ni][0] * SC - mn0) * LOG2E);
            float p1 = exp2f((s[ni][1] * SC - mn0) * LOG2E);
            float p2 = exp2f((s[ni][2] * SC - mn1) * LOG2E);
            float p3 = exp2f((s[ni][3] * SC - mn1) * LOG2E);
            s[ni][0] = p0; s[ni][1] = p1; s[ni][2] = p2; s[ni][3] = p3;
            sum0 += p0 + p1; sum1 += p2 + p3;
            o[ni][0] *= al0; o[ni][1] *= al0; o[ni][2] *= al1; o[ni][3] *= al1;
        }
        sum0 += __shfl_xor_sync(0xffffffffu, sum0, 1);
        sum0 += __shfl_xor_sync(0xffffffffu, sum0, 2);
        sum1 += __shfl_xor_sync(0xffffffffu, sum1, 1);
        sum1 += __shfl_xor_sync(0xffffffffu, sum1, 2);
        l0r = l0r * al0 + sum0;
        l1r = l1r * al1 + sum1;

        // ---- O += P @ V: p_f16 x (v_hi + v_mid)  [2 MMAs per step] ----
        #pragma unroll
        for (int c0 = 0; c0 < 4; c0++) {
            uint32_t ph[4];
            ph[0] = pack_f16(s[2*c0][0],   s[2*c0][1]);
            ph[1] = pack_f16(s[2*c0][2],   s[2*c0][3]);
            ph[2] = pack_f16(s[2*c0+1][0], s[2*c0+1][1]);
            ph[3] = pack_f16(s[2*c0+1][2], s[2*c0+1][3]);
            const int ra = (c0*8 + tr) * VSTR;
            const int rb = ra + 4*VSTR;
            #pragma unroll
            for (int ni = 0; ni < 8; ni++) {
                const int dd = ni*8 + tq;
                uint32_t vh[2], vm[2];
                vh[0] = Vh[ra + dd]; vh[1] = Vh[rb + dd];
                vm[0] = Vm[ra + dd]; vm[1] = Vm[rb + dd];
                mma_f16(o[ni], ph, vh);
                mma_f16(o[ni], ph, vm);
            }
        }
    }

    // ---- epilogue: y = o / l * gate ----
    const int rowa = qt*64 + r0, rowb = rowa + 8;
    float g0 = g_gate[(b*T + rowa) * NH + h] / l0r;
    float g1 = g_gate[(b*T + rowb) * NH + h] / l1r;
    #pragma unroll
    for (int ni = 0; ni < 8; ni++) {
        int col = ni*8 + 2*tr;
        size_t ba = ((size_t)(b*T + rowa) * NH + h) * HD + col;
        size_t bb = ((size_t)(b*T + rowb) * NH + h) * HD + col;
        *(float2*)(g_y + ba) = make_float2(o[ni][0] * g0, o[ni][1] * g0);
        *(float2*)(g_y + bb) = make_float2(o[ni][2] * g1, o[ni][3] * g1);
    }
}

// ---------------- launch ----------------
extern "C" void kernel_launch(void* const* d_in, const int* in_sizes, int n_in,
                              void* d_out, int out_size) {
    (void)in_sizes; (void)n_in; (void)out_size;
    const float* x  = (const float*)d_in[0];
    const float* qw = (const float*)d_in[1];
    const float* kw = (const float*)d_in[2];
    const float* vw = (const float*)d_in[3];
    const float* ow = (const float*)d_in[4];
    const float* ve = (const float*)d_in[5];
    const float* v0 = (const float*)d_in[6];
    const float* qg = (const float*)d_in[7];
    const float* vl = (const float*)d_in[8];
    const float* gw = (const float*)d_in[9];
    const float* gb = (const float*)d_in[10];

    float* out     = (float*)d_out;
    float* raw_out = out + (size_t)B * T * D;     // second output: raw_v

    // NTK-scaled base: T=2048 > TSL=1024
    const double nb = 10000.0 * pow((double)T / 1024.0, 64.0 / 62.0);

    // fused QKV projections (+ V epilogue folded into V tiles)
    gemm_bf16<<<dim3(12, (B*T)/128), 256>>>(x, qw, kw, vw, nullptr, ve, v0, vl,
                                            nullptr, raw_out, 0);

    // rmsnorm + rope (+ q gain) -> packed fp16x2 planes
    rmsnorm_rope_pack<<<(B*T*NH)/8,  256>>>(0, qg,      NH,  nb);
    rmsnorm_rope_pack<<<(B*T*NKV)/8, 256>>>(1, nullptr, NKV, nb);

    // pack mixed V into t-pair fp16 planes
    v_pack<<<(B*NKV*(T/2)*HD)/256, 256>>>();

    // gate
    gate_kernel<<<B*T, 512>>>(x, gw, gb);

    // fp16 tensor-core attention (gate folded into epilogue)
    attn_f16<<<dim3(T/64, NH, B), 128>>>();

    // output projection (bf16 3-pass, proven)
    gemm_bf16<<<dim3(D/128, (B*T)/128), 256>>>(nullptr, nullptr, nullptr, nullptr, ow,
                                               nullptr, nullptr, nullptr, out, nullptr, 1);
}

// round 13
// speedup vs baseline: 1.7022x; 1.0086x over previous
#include <cuda_runtime.h>
#include <cuda_fp16.h>
#include <math.h>
#include <stdint.h>

#define B   2
#define T   2048
#define D   1024
#define NH  16
#define NKV 4
#define HD  64
#define GQ  4            // NH / NKV
#define EPSF 1.1920929e-07f
#define LOG2E 1.4426950408889634f
#define PSTR 12          // GEMM smem word stride (8 data + 4 pad) -> conflict-free frags
#define KSTR 36          // attn K plane stride: 36 mod 32 = 4 -> banks 4tq+tr (perm)
#define VSTR 72          // attn V plane stride: 72 mod 32 = 8 -> banks 8tr+tq (perm)

// ---------------- scratch (no allocations allowed) ----------------
__device__ float    g_q[B*T*NH*HD];        // q projection (fp32)
__device__ float    g_k[B*T*NKV*HD];       // k projection (fp32)
__device__ float    g_v[B*T*NKV*HD];       // v mixed (fp32)
__device__ float    g_y[B*T*NH*HD];        // attention output (gate folded in)
__device__ float    g_gate[B*T*NH];        // sigmoid gate
__device__ uint32_t g_qh[B*T*NH*(HD/2)];   // q normed/roped/gained: packed fp16x2 (hi only)
__device__ uint32_t g_kh[B*T*NKV*(HD/2)];  // k: fp16x2 hi plane
__device__ uint32_t g_km[B*T*NKV*(HD/2)];  // k: fp16x2 residual plane
__device__ uint32_t g_vth[B*NKV*(T/2)*HD]; // v packed along t-pairs: [b][kv][t/2][d] hi
__device__ uint32_t g_vtm[B*NKV*(T/2)*HD]; // ... residual

// ---------------- mma helpers ----------------
__device__ __forceinline__ void mma_bf16(float* c, const uint32_t* a, const uint32_t* b) {
    asm volatile(
        "mma.sync.aligned.m16n8k16.row.col.f32.bf16.bf16.f32 "
        "{%0,%1,%2,%3}, {%4,%5,%6,%7}, {%8,%9}, {%0,%1,%2,%3};\n"
        : "+f"(c[0]), "+f"(c[1]), "+f"(c[2]), "+f"(c[3])
        : "r"(a[0]), "r"(a[1]), "r"(a[2]), "r"(a[3]), "r"(b[0]), "r"(b[1]));
}
__device__ __forceinline__ void mma_f16(float* c, const uint32_t* a, const uint32_t* b) {
    asm volatile(
        "mma.sync.aligned.m16n8k16.row.col.f32.f16.f16.f32 "
        "{%0,%1,%2,%3}, {%4,%5,%6,%7}, {%8,%9}, {%0,%1,%2,%3};\n"
        : "+f"(c[0]), "+f"(c[1]), "+f"(c[2]), "+f"(c[3])
        : "r"(a[0]), "r"(a[1]), "r"(a[2]), "r"(a[3]), "r"(b[0]), "r"(b[1]));
}

// bf16 split: (x0,x1) -> hi word + residual word (GEMM path, proven)
__device__ __forceinline__ void split2_pack(float x0, float x1, uint32_t& wh, uint32_t& wm) {
    asm("cvt.rn.bf16x2.f32 %0, %1, %2;" : "=r"(wh) : "f"(x1), "f"(x0));
    float h0 = __uint_as_float(wh << 16);
    float h1 = __uint_as_float(wh & 0xffff0000u);
    asm("cvt.rn.bf16x2.f32 %0, %1, %2;" : "=r"(wm) : "f"(x1 - h1), "f"(x0 - h0));
}

// fp16 split: (x0,x1) -> hi word + residual word (attention K/V path)
__device__ __forceinline__ void split2_pack_f16(float x0, float x1, uint32_t& wh, uint32_t& wm) {
    __half2 h = __floats2half2_rn(x0, x1);
    wh = *(uint32_t*)&h;
    float2 hf = __half22float2(h);
    __half2 m = __floats2half2_rn(x0 - hf.x, x1 - hf.y);
    wm = *(uint32_t*)&m;
}

// pack two fp32 softmax args and take 2 exponentials in ONE MUFU op
__device__ __forceinline__ uint32_t ex2_pair(float a0, float a1) {
    uint32_t w, r;
    asm("cvt.rn.satfinite.f16x2.f32 %0, %1, %2;" : "=r"(w) : "f"(a1), "f"(a0));
    asm("ex2.approx.f16x2 %0, %1;" : "=r"(r) : "r"(w));
    return r;
}

// ---------------- fused bf16-split GEMM (R9/R10 proven, unchanged) ----------------
// job=0: QKV fused. grid.x: [0,8)=Q, [8,10)=K, [10,12)=V (+v epilogue).
// job=1: O projection (A = g_y, C = out).
__global__ __launch_bounds__(256)
void gemm_bf16(const float* __restrict__ x,  const float* __restrict__ qw,
               const float* __restrict__ kw, const float* __restrict__ vw,
               const float* __restrict__ ow, const float* __restrict__ ve,
               const float* __restrict__ v0, const float* __restrict__ lam,
               float* __restrict__ out, float* __restrict__ raw_out, int job) {
    __shared__ uint32_t Ah[2][128*PSTR], Am[2][128*PSTR];
    __shared__ uint32_t Bh[2][128*PSTR], Bm[2][128*PSTR];

    const float* A; const float* W; float* C = nullptr; int N, n0; bool vjob = false;
    if (job == 0) {
        A = x;
        int bx = blockIdx.x;
        if (bx < 8)       { W = qw; C = g_q; N = NH*HD;  n0 = bx * 128; }
        else if (bx < 10) { W = kw; C = g_k; N = NKV*HD; n0 = (bx - 8) * 128; }
        else              { W = vw; C = g_v; N = NKV*HD; n0 = (bx - 10) * 128; vjob = true; }
    } else {
        A = g_y; W = ow; C = out; N = D; n0 = blockIdx.x * 128;
    }
    const int K = D;
    const int m0 = blockIdx.y * 128;

    const int tid  = threadIdx.x;
    const int lane = tid & 31;
    const int w    = tid >> 5;
    const int wm   = w & 1;
    const int wn   = w >> 1;
    const int tq   = lane >> 2;
    const int tr   = lane & 3;

    const int lrow = tid >> 1;
    const int lc8  = (tid & 1) * 8;
    const int lw   = (tid & 1) * 4;

    const float* aN = A + (size_t)(m0 + lrow) * K + lc8;
    const float* bN = W + (size_t)(n0 + lrow) * K + lc8;

    float c[16][4];
    #pragma unroll
    for (int i = 0; i < 16; i++)
        #pragma unroll
        for (int j = 0; j < 4; j++) c[i][j] = 0.f;

    {
        float4 a0 = *(const float4*)(aN);
        float4 a1 = *(const float4*)(aN + 4);
        float4 b0 = *(const float4*)(bN);
        float4 b1 = *(const float4*)(bN + 4);
        uint32_t h[4], m[4];
        split2_pack(a0.x, a0.y, h[0], m[0]); split2_pack(a0.z, a0.w, h[1], m[1]);
        split2_pack(a1.x, a1.y, h[2], m[2]); split2_pack(a1.z, a1.w, h[3], m[3]);
        *(uint4*)&Ah[0][lrow*PSTR + lw] = make_uint4(h[0], h[1], h[2], h[3]);
        *(uint4*)&Am[0][lrow*PSTR + lw] = make_uint4(m[0], m[1], m[2], m[3]);
        split2_pack(b0.x, b0.y, h[0], m[0]); split2_pack(b0.z, b0.w, h[1], m[1]);
        split2_pack(b1.x, b1.y, h[2], m[2]); split2_pack(b1.z, b1.w, h[3], m[3]);
        *(uint4*)&Bh[0][lrow*PSTR + lw] = make_uint4(h[0], h[1], h[2], h[3]);
        *(uint4*)&Bm[0][lrow*PSTR + lw] = make_uint4(m[0], m[1], m[2], m[3]);
    }
    __syncthreads();

    const int niter = K / 16;
    int cur = 0;
    for (int it = 0; it < niter; it++) {
        float4 pa0, pa1, pb0, pb1;
        const bool has_next = (it + 1 < niter);
        if (has_next) {
            int k0 = (it + 1) * 16;
            pa0 = *(const float4*)(aN + k0);
            pa1 = *(const float4*)(aN + k0 + 4);
            pb0 = *(const float4*)(bN + k0);
            pb1 = *(const float4*)(bN + k0 + 4);
        }

        const uint32_t* ah = Ah[cur]; const uint32_t* am = Am[cur];
        const uint32_t* bh = Bh[cur]; const uint32_t* bm = Bm[cur];

        uint32_t afh[4][4], afm[4][4], bfh[4][2], bfm[4][2];
        #pragma unroll
        for (int mi = 0; mi < 4; mi++) {
            int r = wm * 64 + mi * 16 + tq;
            afh[mi][0] = ah[r*PSTR + tr];     afh[mi][1] = ah[(r+8)*PSTR + tr];
            afh[mi][2] = ah[r*PSTR + tr + 4]; afh[mi][3] = ah[(r+8)*PSTR + tr + 4];
            afm[mi][0] = am[r*PSTR + tr];     afm[mi][1] = am[(r+8)*PSTR + tr];
            afm[mi][2] = am[r*PSTR + tr + 4]; afm[mi][3] = am[(r+8)*PSTR + tr + 4];
        }
        #pragma unroll
        for (int ni = 0; ni < 4; ni++) {
            int rn = wn * 32 + ni * 8 + tq;
            bfh[ni][0] = bh[rn*PSTR + tr]; bfh[ni][1] = bh[rn*PSTR + tr + 4];
            bfm[ni][0] = bm[rn*PSTR + tr]; bfm[ni][1] = bm[rn*PSTR + tr + 4];
        }
        #pragma unroll
        for (int mi = 0; mi < 4; mi++)
            #pragma unroll
            for (int ni = 0; ni < 4; ni++) {
                mma_bf16(c[mi*4+ni], afh[mi], bfh[ni]);
                mma_bf16(c[mi*4+ni], afh[mi], bfm[ni]);
                mma_bf16(c[mi*4+ni], afm[mi], bfh[ni]);
            }

        if (has_next) {
            int nxt = cur ^ 1;
            uint32_t h[4], m[4];
            split2_pack(pa0.x, pa0.y, h[0], m[0]); split2_pack(pa0.z, pa0.w, h[1], m[1]);
            split2_pack(pa1.x, pa1.y, h[2], m[2]); split2_pack(pa1.z, pa1.w, h[3], m[3]);
            *(uint4*)&Ah[nxt][lrow*PSTR + lw] = make_uint4(h[0], h[1], h[2], h[3]);
            *(uint4*)&Am[nxt][lrow*PSTR + lw] = make_uint4(m[0], m[1], m[2], m[3]);
            split2_pack(pb0.x, pb0.y, h[0], m[0]); split2_pack(pb0.z, pb0.w, h[1], m[1]);
            split2_pack(pb1.x, pb1.y, h[2], m[2]); split2_pack(pb1.z, pb1.w, h[3], m[3]);
            *(uint4*)&Bh[nxt][lrow*PSTR + lw] = make_uint4(h[0], h[1], h[2], h[3]);
            *(uint4*)&Bm[nxt][lrow*PSTR + lw] = make_uint4(m[0], m[1], m[2], m[3]);
            __syncthreads();
            cur = nxt;
        }
    }

    if (!vjob) {
        #pragma unroll
        for (int mi = 0; mi < 4; mi++)
            #pragma unroll
            for (int ni = 0; ni < 4; ni++) {
                int row = m0 + wm*64 + mi*16 + tq;
                int col = n0 + wn*32 + ni*8 + 2*tr;
                float* cp = c[mi*4+ni];
                *(float2*)(C + (size_t)row * N + col)       = make_float2(cp[0], cp[1]);
                *(float2*)(C + (size_t)(row + 8) * N + col) = make_float2(cp[2], cp[3]);
            }
    } else {
        const float l0 = lam[0], l1 = lam[1];
        #pragma unroll
        for (int mi = 0; mi < 4; mi++)
            #pragma unroll
            for (int ni = 0; ni < 4; ni++) {
                int row = m0 + wm*64 + mi*16 + tq;
                int col = n0 + wn*32 + ni*8 + 2*tr;
                float* cp = c[mi*4+ni];
                #pragma unroll
                for (int half = 0; half < 2; half++) {
                    size_t gi = (size_t)(row + half*8) * N + col;
                    float2 vee = *(const float2*)(ve + gi);
                    float2 v00 = *(const float2*)(v0 + gi);
                    float r0 = cp[half*2]   + vee.x;
                    float r1 = cp[half*2+1] + vee.y;
                    *(float2*)(raw_out + gi) = make_float2(r0, r1);
                    *(float2*)(C + gi) = make_float2(l0*v00.x + l1*r0, l0*v00.y + l1*r1);
                }
            }
    }
}

// ---------------- RMSNorm + RoPE (+gain), emit packed fp16x2 planes ----------------
// buf 0: Q -> g_qh only (fp16). buf 1: K -> g_kh + g_km (hi + residual).
__global__ void rmsnorm_rope_pack(int buf, const float* __restrict__ gain, int H, double nb) {
    const float* src = (buf == 0) ? g_q : g_k;

    int row  = blockIdx.x * 8 + (threadIdx.x >> 5);
    int lane = threadIdx.x & 31;
    int t = (row / H) % T;
    int h = row % H;
    const float* p = src + (size_t)row * HD;

    float a  = p[lane];
    float b2 = p[lane + 32];
    float ss = a*a + b2*b2;
    #pragma unroll
    for (int o = 16; o; o >>= 1) ss += __shfl_xor_sync(0xffffffffu, ss, o);
    float r = rsqrtf(ss * (1.0f/HD) + EPSF);
    a *= r; b2 *= r;

    float inv = (float)pow(nb, -(double)(2*lane) / (double)HD);
    float fr  = (float)t * inv;
    float cc = (float)cos((double)fr);
    float sn = (float)sin((double)fr);

    float o1 =  a*cc + b2*sn;          // d = lane
    float o2 = -a*sn + b2*cc;          // d = lane + 32
    if (gain) { float gg = gain[h]; o1 *= gg; o2 *= gg; }

    float p1 = __shfl_xor_sync(0xffffffffu, o1, 1);
    float p2 = __shfl_xor_sync(0xffffffffu, o2, 1);
    uint32_t wh, wmv; int widx;
    if (lane & 1) { split2_pack_f16(p2, o2, wh, wmv); widx = 16 + (lane >> 1); }
    else          { split2_pack_f16(o1, p1, wh, wmv); widx = lane >> 1; }
    if (buf == 0) {
        g_qh[(size_t)row * 32 + widx] = wh;
    } else {
        g_kh[(size_t)row * 32 + widx] = wh;
        g_km[(size_t)row * 32 + widx] = wmv;
    }
}

// ---------------- V pack: g_v [b][t][kv][d] -> t-pair packed fp16 planes ----------------
__global__ void v_pack() {
    int idx = blockIdx.x * 256 + threadIdx.x;
    int d  = idx & 63;
    int tp = (idx >> 6) & (T/2 - 1);
    int kv = (idx >> 16) & 3;
    int b  = idx >> 18;
    float a  = g_v[((size_t)(b*T + 2*tp)     * NKV + kv) * HD + d];
    float b2 = g_v[((size_t)(b*T + 2*tp + 1) * NKV + kv) * HD + d];
    uint32_t wh, wmv;
    split2_pack_f16(a, b2, wh, wmv);
    g_vth[idx] = wh;
    g_vtm[idx] = wmv;
}

// ---------------- gate: sigmoid(x @ gate_w^T + gate_b), one block per (b,t) ----------------
__global__ void gate_kernel(const float* __restrict__ x, const float* __restrict__ gw,
                            const float* __restrict__ gb) {
    __shared__ float xs[D];
    int bt = blockIdx.x;
    for (int i = threadIdx.x; i < D; i += 512) xs[i] = x[(size_t)bt * D + i];
    __syncthreads();
    int h = threadIdx.x >> 5, lane = threadIdx.x & 31;
    const float* w = gw + (size_t)h * D;
    float s = 0.f;
    for (int i = lane; i < D; i += 32) s += xs[i] * w[i];
    #pragma unroll
    for (int o = 16; o; o >>= 1) s += __shfl_xor_sync(0xffffffffu, s, o);
    if (lane == 0) g_gate[bt * NH + h] = 1.0f / (1.0f + __expf(-(s + gb[h])));
}

// ---------------- fp16 flash attention: paired EX2 softmax + ones-MMA row sums ----------------
__global__ __launch_bounds__(128)
void attn_f16() {
    __shared__ uint32_t Kh[64*KSTR], Km[64*KSTR];   // [key n][k/2 word]
    __shared__ uint32_t Vh[32*VSTR], Vm[32*VSTR];   // [t-pair][d]

    const int qt = (int)gridDim.x - 1 - (int)blockIdx.x;   // heavy tiles first
    const int h = blockIdx.y, b = blockIdx.z;
    const int kv = h / GQ;
    const int tid = threadIdx.x;
    const int w = tid >> 5, lane = tid & 31;
    const int tq = lane >> 2, tr = lane & 3;
    const int r0 = w * 16 + tq;

    // persistent Q fragments (fp16) from packed plane
    uint32_t qh[4][4];
    {
        const size_t qA = ((size_t)(b*T + qt*64 + r0) * NH + h) * 32;
        const size_t qB = qA + (size_t)8 * NH * 32;
        #pragma unroll
        for (int kb = 0; kb < 4; kb++) {
            qh[kb][0] = g_qh[qA + kb*8 + tr];     qh[kb][1] = g_qh[qB + kb*8 + tr];
            qh[kb][2] = g_qh[qA + kb*8 + tr + 4]; qh[kb][3] = g_qh[qB + kb*8 + tr + 4];
        }
    }

    float o[8][4];
    #pragma unroll
    for (int ni = 0; ni < 8; ni++)
        #pragma unroll
        for (int j = 0; j < 4; j++) o[ni][j] = 0.f;
    float m0r = -1e30f, m1r = -1e30f, l0r = 0.f, l1r = 0.f;

    const size_t kbase = ((size_t)(b*T) * NKV + kv) * 32;
    const size_t vbase = ((size_t)(b*NKV + kv)) * (T/2) * 64;
    const uint32_t ONES = 0x3C003C00u;
    uint32_t bones[2] = {ONES, ONES};

    for (int kt = 0; kt <= qt; kt++) {
        const int t0 = kt * 64;
        __syncthreads();
        #pragma unroll
        for (int ci = 0; ci < 4; ci++) {
            int i = tid + ci * 128;
            int r = i >> 3, j = (i & 7) * 4;
            size_t src = kbase + (size_t)(t0 + r) * (NKV*32) + j;
            *(uint4*)&Kh[r*KSTR + j] = *(const uint4*)&g_kh[src];
            *(uint4*)&Km[r*KSTR + j] = *(const uint4*)&g_km[src];
        }
        #pragma unroll
        for (int ci = 0; ci < 4; ci++) {
            int i = tid + ci * 128;
            int tp = i >> 4, j = (i & 15) * 4;
            size_t src = vbase + (size_t)(t0/2 + tp) * 64 + j;
            *(uint4*)&Vh[tp*VSTR + j] = *(const uint4*)&g_vth[src];
            *(uint4*)&Vm[tp*VSTR + j] = *(const uint4*)&g_vtm[src];
        }
        __syncthreads();

        // ---- S = Q @ K^T: q_f16 x (k_hi + k_mid) ----
        float s[8][4];
        #pragma unroll
        for (int ni = 0; ni < 8; ni++) {
            s[ni][0] = s[ni][1] = s[ni][2] = s[ni][3] = 0.f;
            const int kn = (ni*8 + tq) * KSTR;
            #pragma unroll
            for (int kb = 0; kb < 4; kb++) {
                uint32_t bh[2], bm[2];
                bh[0] = Kh[kn + kb*8 + tr]; bh[1] = Kh[kn + kb*8 + tr + 4];
                bm[0] = Km[kn + kb*8 + tr]; bm[1] = Km[kn + kb*8 + tr + 4];
                mma_f16(s[ni], qh[kb], bh);
                mma_f16(s[ni], qh[kb], bm);
            }
        }

        // ---- causal mask (diagonal tile only) ----
        const int rowa = qt*64 + r0, rowb = rowa + 8;
        if (kt == qt) {
            #pragma unroll
            for (int ni = 0; ni < 8; ni++) {
                int col = t0 + ni*8 + 2*tr;
                if (col     > rowa) s[ni][0] = -1e30f;
                if (col + 1 > rowa) s[ni][1] = -1e30f;
                if (col     > rowb) s[ni][2] = -1e30f;
                if (col + 1 > rowb) s[ni][3] = -1e30f;
            }
        }

        // ---- online softmax: row max in fp32, exps as fp16 PAIRS (1 MUFU / 2 vals) ----
        const float SC = 0.125f;
        float mx0 = -1e30f, mx1 = -1e30f;
        #pragma unroll
        for (int ni = 0; ni < 8; ni++) {
            mx0 = fmaxf(mx0, fmaxf(s[ni][0], s[ni][1]));
            mx1 = fmaxf(mx1, fmaxf(s[ni][2], s[ni][3]));
        }
        mx0 = fmaxf(mx0, __shfl_xor_sync(0xffffffffu, mx0, 1));
        mx0 = fmaxf(mx0, __shfl_xor_sync(0xffffffffu, mx0, 2));
        mx1 = fmaxf(mx1, __shfl_xor_sync(0xffffffffu, mx1, 1));
        mx1 = fmaxf(mx1, __shfl_xor_sync(0xffffffffu, mx1, 2));
        float mn0 = fmaxf(m0r, mx0 * SC);
        float mn1 = fmaxf(m1r, mx1 * SC);
        float al0 = exp2f((m0r - mn0) * LOG2E);
        float al1 = exp2f((m1r - mn1) * LOG2E);
        m0r = mn0; m1r = mn1;

        const float cf = SC * LOG2E;
        const float d0 = mn0 * LOG2E;
        const float d1 = mn1 * LOG2E;
        uint32_t pw[8][2];
        #pragma unroll
        for (int ni = 0; ni < 8; ni++) {
            pw[ni][0] = ex2_pair(fmaf(s[ni][0], cf, -d0), fmaf(s[ni][1], cf, -d0));
            pw[ni][1] = ex2_pair(fmaf(s[ni][2], cf, -d1), fmaf(s[ni][3], cf, -d1));
            o[ni][0] *= al0; o[ni][1] *= al0; o[ni][2] *= al1; o[ni][3] *= al1;
        }

        // ---- O += P @ V and l += P @ ones (row sums on tensor pipe) ----
        float lacc[4] = {0.f, 0.f, 0.f, 0.f};
        #pragma unroll
        for (int c0 = 0; c0 < 4; c0++) {
            uint32_t ph[4] = {pw[2*c0][0], pw[2*c0][1], pw[2*c0+1][0], pw[2*c0+1][1]};
            mma_f16(lacc, ph, bones);
            const int ra = (c0*8 + tr) * VSTR;
            const int rb = ra + 4*VSTR;
            #pragma unroll
            for (int ni = 0; ni < 8; ni++) {
                const int dd = ni*8 + tq;
                uint32_t vh[2], vm[2];
                vh[0] = Vh[ra + dd]; vh[1] = Vh[rb + dd];
                vm[0] = Vm[ra + dd]; vm[1] = Vm[rb + dd];
                mma_f16(o[ni], ph, vh);
                mma_f16(o[ni], ph, vm);
            }
        }
        l0r = l0r * al0 + lacc[0];
        l1r = l1r * al1 + lacc[2];
    }

    // ---- epilogue: y = o / l * gate ----
    const int rowa = qt*64 + r0, rowb = rowa + 8;
    float g0 = g_gate[(b*T + rowa) * NH + h] / l0r;
    float g1 = g_gate[(b*T + rowb) * NH + h] / l1r;
    #pragma unroll
    for (int ni = 0; ni < 8; ni++) {
        int col = ni*8 + 2*tr;
        size_t ba = ((size_t)(b*T + rowa) * NH + h) * HD + col;
        size_t bb = ((size_t)(b*T + rowb) * NH + h) * HD + col;
        *(float2*)(g_y + ba) = make_float2(o[ni][0] * g0, o[ni][1] * g0);
        *(float2*)(g_y + bb) = make_float2(o[ni][2] * g1, o[ni][3] * g1);
    }
}

// ---------------- launch ----------------
extern "C" void kernel_launch(void* const* d_in, const int* in_sizes, int n_in,
                              void* d_out, int out_size) {
    (void)in_sizes; (void)n_in; (void)out_size;
    const float* x  = (const float*)d_in[0];
    const float* qw = (const float*)d_in[1];
    const float* kw = (const float*)d_in[2];
    const float* vw = (const float*)d_in[3];
    const float* ow = (const float*)d_in[4];
    const float* ve = (const float*)d_in[5];
    const float* v0 = (const float*)d_in[6];
    const float* qg = (const float*)d_in[7];
    const float* vl = (const float*)d_in[8];
    const float* gw = (const float*)d_in[9];
    const float* gb = (const float*)d_in[10];

    float* out     = (float*)d_out;
    float* raw_out = out + (size_t)B * T * D;     // second output: raw_v

    // NTK-scaled base: T=2048 > TSL=1024
    const double nb = 10000.0 * pow((double)T / 1024.0, 64.0 / 62.0);

    // fused QKV projections (+ V epilogue folded into V tiles)
    gemm_bf16<<<dim3(12, (B*T)/128), 256>>>(x, qw, kw, vw, nullptr, ve, v0, vl,
                                            nullptr, raw_out, 0);

    // rmsnorm + rope (+ q gain) -> packed fp16x2 planes
    rmsnorm_rope_pack<<<(B*T*NH)/8,  256>>>(0, qg,      NH,  nb);
    rmsnorm_rope_pack<<<(B*T*NKV)/8, 256>>>(1, nullptr, NKV, nb);

    // pack mixed V into t-pair fp16 planes
    v_pack<<<(B*NKV*(T/2)*HD)/256, 256>>>();

    // gate
    gate_kernel<<<B*T, 512>>>(x, gw, gb);

    // fp16 tensor-core attention (gate folded into epilogue)
    attn_f16<<<dim3(T/64, NH, B), 128>>>();

    // output projection (bf16 3-pass, proven)
    gemm_bf16<<<dim3(D/128, (B*T)/128), 256>>>(nullptr, nullptr, nullptr, nullptr, ow,
                                               nullptr, nullptr, nullptr, out, nullptr, 1);
}